// round 1
// baseline (speedup 1.0000x reference)
#include <cuda_runtime.h>

#define BN 8
#define NP 8192
#define SS 512
#define SA 128
#define SNN 384
#define KK 64
#define DF 64
#define C0 67
#define QPB 4

__device__ int g_nbr[BN * SS * KK];

// ---------------------------------------------------------------------------
// FPS: one block per (batch, {attn,none}). Per-thread coords/min_d2 in regs.
// Matches jax.lax.scan semantics: emit `last` (starting at 0), then update.
// Tie-break: first (lowest-index) max, matching jnp.argmax.
// ---------------------------------------------------------------------------
__global__ __launch_bounds__(1024, 1) void fps_kernel(
    const float* __restrict__ xyz, const float* __restrict__ attn,
    float* __restrict__ out_xyz, float* __restrict__ out_attn)
{
    extern __shared__ float sm[];
    float* xs = sm;
    float* ys = sm + NP;
    float* zs = sm + 2 * NP;
    __shared__ float rv[32];
    __shared__ int   ri[32];
    __shared__ int   s_last;

    const int tid  = threadIdx.x;
    const int lane = tid & 31, wid = tid >> 5;
    const int b = blockIdx.y;
    const int which = blockIdx.x;          // 0 = attn (128), 1 = none (384)
    const int Ksel = (which == 0) ? SA : SNN;
    const int off  = (which == 0) ? 0 : SA;

    const float* xb = xyz + (size_t)b * 3 * NP;
    const float* ab = attn + (size_t)b * NP;

    float px[8], py[8], pz[8], md[8];
#pragma unroll
    for (int j = 0; j < 8; j++) {
        int i = tid + j * 1024;
        float a = ab[i];
        float f = (which == 0) ? a : 1.0f - a;
        float x = f * xb[i], y = f * xb[NP + i], z = f * xb[2 * NP + i];
        px[j] = x; py[j] = y; pz[j] = z; md[j] = 1e10f;
        xs[i] = x; ys[i] = y; zs[i] = z;
    }
    __syncthreads();

    int last = 0;
    for (int k = 0;; k++) {
        if (tid == 0) {
            int o = off + k;
            out_xyz[(size_t)b * 3 * SS + o]          = xs[last];
            out_xyz[(size_t)b * 3 * SS + SS + o]     = ys[last];
            out_xyz[(size_t)b * 3 * SS + 2 * SS + o] = zs[last];
            out_attn[(size_t)b * SS + o] = ab[last];
        }
        if (k == Ksel - 1) break;

        float lx = xs[last], ly = ys[last], lz = zs[last];
        float bv = -1.0f; int bi = NP;
#pragma unroll
        for (int j = 0; j < 8; j++) {
            float dx = px[j] - lx, dy = py[j] - ly, dz = pz[j] - lz;
            float d2 = fmaf(dz, dz, fmaf(dy, dy, dx * dx));
            float m = fminf(md[j], d2);
            md[j] = m;
            if (m > bv) { bv = m; bi = tid + j * 1024; }  // j ascending => first-max in-thread
        }
#pragma unroll
        for (int o2 = 16; o2 > 0; o2 >>= 1) {
            float ov = __shfl_down_sync(0xffffffffu, bv, o2);
            int   oi = __shfl_down_sync(0xffffffffu, bi, o2);
            if (ov > bv || (ov == bv && oi < bi)) { bv = ov; bi = oi; }
        }
        if (lane == 0) { rv[wid] = bv; ri[wid] = bi; }
        __syncthreads();
        if (wid == 0) {
            bv = rv[lane]; bi = ri[lane];
#pragma unroll
            for (int o2 = 16; o2 > 0; o2 >>= 1) {
                float ov = __shfl_down_sync(0xffffffffu, bv, o2);
                int   oi = __shfl_down_sync(0xffffffffu, bi, o2);
                if (ov > bv || (ov == bv && oi < bi)) { bv = ov; bi = oi; }
            }
            if (lane == 0) s_last = bi;
        }
        __syncthreads();
        last = s_last;
    }
}

// ---------------------------------------------------------------------------
// Ball query: one warp per query. First KK points (index order) with d2 < r^2,
// pad -1. Ordered chunks of 32 + ballot prefix keep exact index-order.
// ---------------------------------------------------------------------------
__global__ __launch_bounds__(256, 1) void ball_kernel(
    const float* __restrict__ xyz, const float* __restrict__ new_xyz)
{
    int w = blockIdx.x * 8 + (threadIdx.x >> 5);
    int lane = threadIdx.x & 31;
    int b = w >> 9, s = w & 511;
    const float R2 = (float)(0.4 * 0.4);

    float qx = new_xyz[(size_t)b * 3 * SS + s];
    float qy = new_xyz[(size_t)b * 3 * SS + SS + s];
    float qz = new_xyz[(size_t)b * 3 * SS + 2 * SS + s];
    const float* xb = xyz + (size_t)b * 3 * NP;
    int* out = g_nbr + (size_t)w * KK;

    int cnt = 0;
    for (int base = 0; base < NP; base += 32) {
        int i = base + lane;
        float dx = xb[i] - qx, dy = xb[NP + i] - qy, dz = xb[2 * NP + i] - qz;
        float d2 = fmaf(dz, dz, fmaf(dy, dy, dx * dx));
        bool m = d2 < R2;
        unsigned bal = __ballot_sync(0xffffffffu, m);
        int rank = cnt + __popc(bal & ((1u << lane) - 1u));
        if (m && rank < KK) out[rank] = i;
        cnt += __popc(bal);
        if (cnt >= KK) break;
    }
    if (cnt > KK) cnt = KK;
    for (int j = cnt + lane; j < KK; j += 32) out[j] = -1;
}

// ---------------------------------------------------------------------------
// MLP 67->64->64->128 + ReLU + max over K. Block = QPB queries x 64 neighbors.
// Weights in smem (broadcast LDS); hidden acts in thread-private smem column.
// Invalid slot: norm = -query, features = points[:, N-1] (torch -1 wrap).
// ---------------------------------------------------------------------------
__global__ __launch_bounds__(256, 1) void mlp_kernel(
    const float* __restrict__ xyz, const float* __restrict__ pts,
    const float* __restrict__ w0, const float* __restrict__ b0,
    const float* __restrict__ w1, const float* __restrict__ b1,
    const float* __restrict__ w2, const float* __restrict__ b2,
    const float* __restrict__ new_xyz, float* __restrict__ out_pts)
{
    extern __shared__ float sm[];
    float* sw0  = sm;               // 4288
    float* sw1  = sw0 + 4288;       // 4096
    float* sw2  = sw1 + 4096;       // 8192
    float* sb0  = sw2 + 8192;       // 64
    float* sb1  = sb0 + 64;         // 64
    float* sb2  = sb1 + 64;         // 128
    float* hbuf = sb2 + 128;        // QPB*64*64
    float* wmax = hbuf + QPB * 4096; // QPB*128*2

    int tid = threadIdx.x;
    for (int i = tid; i < 4288; i += 256) sw0[i] = w0[i];
    for (int i = tid; i < 4096; i += 256) sw1[i] = w1[i];
    for (int i = tid; i < 8192; i += 256) sw2[i] = w2[i];
    if (tid < 64)  sb0[tid] = b0[tid];
    if (tid < 64)  sb1[tid] = b1[tid];
    if (tid < 128) sb2[tid] = b2[tid];

    int ql = tid >> 6;
    int k = tid & 63;
    int lane = tid & 31;
    int half = (tid >> 5) & 1;
    int qg = blockIdx.x * QPB + ql;
    int b = qg >> 9, s = qg & 511;

    float qx = new_xyz[(size_t)b * 3 * SS + s];
    float qy = new_xyz[(size_t)b * 3 * SS + SS + s];
    float qz = new_xyz[(size_t)b * 3 * SS + 2 * SS + s];

    int id = g_nbr[(size_t)qg * KK + k];
    int gid = (id < 0) ? (NP - 1) : id;

    float fin[C0];
    if (id < 0) {
        fin[0] = -qx; fin[1] = -qy; fin[2] = -qz;
    } else {
        const float* xb = xyz + (size_t)b * 3 * NP;
        fin[0] = xb[gid] - qx; fin[1] = xb[NP + gid] - qy; fin[2] = xb[2 * NP + gid] - qz;
    }
    const float* pb = pts + (size_t)b * DF * NP + gid;
#pragma unroll
    for (int d = 0; d < DF; d++) fin[3 + d] = pb[(size_t)d * NP];

    __syncthreads();  // weights ready

    float* hq = hbuf + ql * 4096;

#pragma unroll 2
    for (int o = 0; o < 64; o++) {
        const float* wr = sw0 + o * C0;
        float acc = sb0[o];
#pragma unroll
        for (int c = 0; c < C0; c++) acc = fmaf(wr[c], fin[c], acc);
        hq[o * 64 + k] = fmaxf(acc, 0.0f);
    }
    float r1[64];
#pragma unroll
    for (int c = 0; c < 64; c++) r1[c] = hq[c * 64 + k];
#pragma unroll 2
    for (int o = 0; o < 64; o++) {
        const float* wr = sw1 + o * 64;
        float acc = sb1[o];
#pragma unroll
        for (int c = 0; c < 64; c++) acc = fmaf(wr[c], r1[c], acc);
        hq[o * 64 + k] = fmaxf(acc, 0.0f);
    }
    float r2[64];
#pragma unroll
    for (int c = 0; c < 64; c++) r2[c] = hq[c * 64 + k];
#pragma unroll 2
    for (int o = 0; o < 128; o++) {
        const float* wr = sw2 + o * 64;
        float acc = sb2[o];
#pragma unroll
        for (int c = 0; c < 64; c++) acc = fmaf(wr[c], r2[c], acc);
        float r = fmaxf(acc, 0.0f);
#pragma unroll
        for (int off2 = 16; off2 > 0; off2 >>= 1)
            r = fmaxf(r, __shfl_xor_sync(0xffffffffu, r, off2));
        if (lane == 0) wmax[(ql * 128 + o) * 2 + half] = r;
    }
    __syncthreads();

    for (int j = tid; j < QPB * 128; j += 256) {
        int qq = j >> 7, o = j & 127;
        int qg2 = blockIdx.x * QPB + qq;
        int bb = qg2 >> 9, ss2 = qg2 & 511;
        out_pts[(size_t)bb * 128 * SS + (size_t)o * SS + ss2] =
            fmaxf(wmax[(qq * 128 + o) * 2], wmax[(qq * 128 + o) * 2 + 1]);
    }
}

// ---------------------------------------------------------------------------
extern "C" void kernel_launch(void* const* d_in, const int* in_sizes, int n_in,
                              void* d_out, int out_size)
{
    const float* xyz  = (const float*)d_in[0];
    const float* pts  = (const float*)d_in[1];
    const float* attn = (const float*)d_in[2];
    const float* w0   = (const float*)d_in[3];
    const float* b0   = (const float*)d_in[4];
    const float* w1   = (const float*)d_in[5];
    const float* b1   = (const float*)d_in[6];
    const float* w2   = (const float*)d_in[7];
    const float* b2   = (const float*)d_in[8];

    float* out      = (float*)d_out;
    float* out_xyz  = out;                               // [B,3,S]
    float* out_pts  = out + BN * 3 * SS;                 // [B,128,S]
    float* out_attn = out + BN * 3 * SS + BN * 128 * SS; // [B,1,S]

    size_t fps_smem = (size_t)3 * NP * sizeof(float);    // 96 KB
    size_t mlp_smem = (size_t)(4288 + 4096 + 8192 + 64 + 64 + 128 +
                               QPB * 4096 + QPB * 256) * sizeof(float); // ~134 KB

    cudaFuncSetAttribute(fps_kernel, cudaFuncAttributeMaxDynamicSharedMemorySize, (int)fps_smem);
    cudaFuncSetAttribute(mlp_kernel, cudaFuncAttributeMaxDynamicSharedMemorySize, (int)mlp_smem);

    fps_kernel<<<dim3(2, BN), 1024, fps_smem>>>(xyz, attn, out_xyz, out_attn);
    ball_kernel<<<BN * SS / 8, 256>>>(xyz, out_xyz);
    mlp_kernel<<<BN * SS / QPB, 256, mlp_smem>>>(xyz, pts, w0, b0, w1, b1, w2, b2,
                                                 out_xyz, out_pts);
}

// round 2
// speedup vs baseline: 1.3422x; 1.3422x over previous
#include <cuda_runtime.h>

#define BN 8
#define NP 8192
#define SS 512
#define SA 128
#define SNN 384
#define KK 64
#define DF 64
#define C0 67

__device__ int g_nbr[BN * SS * KK];

// ---------------------------------------------------------------------------
// FPS: one block per (batch, {attn,none}). 512 threads, 16 pts/thread.
// d2 via expansion: |p|^2 - 2 p.l + |l|^2  (3 FFMA seeded with |p|^2, + FADD).
// Value-only warp reduction (REDUX); index recovered by equality scan on the
// (rare) matching threads + atomicMin -> exact lowest-index tie-break, which
// matters because ~half the points collapse to (0,0,0) duplicates.
// ---------------------------------------------------------------------------
__global__ __launch_bounds__(512, 1) void fps_kernel(
    const float* __restrict__ xyz, const float* __restrict__ attn,
    float* __restrict__ out_xyz, float* __restrict__ out_attn)
{
    extern __shared__ float sm[];
    float* xs = sm;
    float* ys = sm + NP;
    float* zs = sm + 2 * NP;
    __shared__ unsigned warpmax[16];
    __shared__ int s_best[2];

    const int tid  = threadIdx.x;
    const int lane = tid & 31, wid = tid >> 5;
    const int b = blockIdx.y;
    const int which = blockIdx.x;          // 0 = attn (128), 1 = none (384)
    const int Ksel = (which == 0) ? SA : SNN;
    const int off  = (which == 0) ? 0 : SA;

    const float* xb = xyz + (size_t)b * 3 * NP;
    const float* ab = attn + (size_t)b * NP;

    float px[16], py[16], pz[16], pn[16], md[16];
#pragma unroll
    for (int j = 0; j < 16; j++) {
        int i = tid + j * 512;
        float a = ab[i];
        float f = (which == 0) ? a : 1.0f - a;
        float x = f * xb[i], y = f * xb[NP + i], z = f * xb[2 * NP + i];
        px[j] = x; py[j] = y; pz[j] = z;
        pn[j] = fmaf(z, z, fmaf(y, y, x * x));
        md[j] = 1e10f;
        xs[i] = x; ys[i] = y; zs[i] = z;
    }
    if (tid == 0) { s_best[0] = 0x7fffffff; s_best[1] = 0x7fffffff; }
    __syncthreads();

    int last = 0;
    int parity = 0;
    for (int k = 0;; k++) {
        float lx = xs[last], ly = ys[last], lz = zs[last];
        if (tid == 0) {
            int o = off + k;
            out_xyz[(size_t)b * 3 * SS + o]          = lx;
            out_xyz[(size_t)b * 3 * SS + SS + o]     = ly;
            out_xyz[(size_t)b * 3 * SS + 2 * SS + o] = lz;
            out_attn[(size_t)b * SS + o] = ab[last];
        }
        if (k == Ksel - 1) break;

        float lx2 = -2.0f * lx, ly2 = -2.0f * ly, lz2 = -2.0f * lz;
        float ln = fmaf(lz, lz, fmaf(ly, ly, lx * lx));

        float tmax = -1e30f;
#pragma unroll
        for (int j = 0; j < 16; j++) {
            float e = fmaf(pz[j], lz2, fmaf(py[j], ly2, fmaf(px[j], lx2, pn[j])));
            float m = fminf(md[j], e + ln);
            md[j] = m;
            tmax = fmaxf(tmax, m);
        }
        unsigned tc = __float_as_uint(fmaxf(tmax, 0.0f));
        unsigned wm = __reduce_max_sync(0xffffffffu, tc);
        if (lane == 0) warpmax[wid] = wm;
        __syncthreads();

        if (tid == 0) s_best[parity ^ 1] = 0x7fffffff;
        unsigned W = warpmax[0];
#pragma unroll
        for (int w = 1; w < 16; w++) W = max(W, warpmax[w]);

        if (tc == W) {
            float Wf = __uint_as_float(W);
            int bi = 0x7fffffff;
#pragma unroll
            for (int j = 0; j < 16; j++)
                bi = min(bi, (md[j] == Wf) ? (tid + j * 512) : 0x7fffffff);
            atomicMin(&s_best[parity], bi);
        }
        __syncthreads();
        last = s_best[parity];
        parity ^= 1;
    }
}

// ---------------------------------------------------------------------------
// Ball query: one warp per query, first KK in index order, pad -1.
// ---------------------------------------------------------------------------
__global__ __launch_bounds__(256, 1) void ball_kernel(
    const float* __restrict__ xyz, const float* __restrict__ new_xyz)
{
    int w = blockIdx.x * 8 + (threadIdx.x >> 5);
    int lane = threadIdx.x & 31;
    int b = w >> 9, s = w & 511;
    const float R2 = (float)(0.4 * 0.4);

    float qx = new_xyz[(size_t)b * 3 * SS + s];
    float qy = new_xyz[(size_t)b * 3 * SS + SS + s];
    float qz = new_xyz[(size_t)b * 3 * SS + 2 * SS + s];
    const float* xb = xyz + (size_t)b * 3 * NP;
    int* out = g_nbr + (size_t)w * KK;

    int cnt = 0;
    for (int base = 0; base < NP; base += 32) {
        int i = base + lane;
        float dx = xb[i] - qx, dy = xb[NP + i] - qy, dz = xb[2 * NP + i] - qz;
        float d2 = fmaf(dz, dz, fmaf(dy, dy, dx * dx));
        bool m = d2 < R2;
        unsigned bal = __ballot_sync(0xffffffffu, m);
        int rank = cnt + __popc(bal & ((1u << lane) - 1u));
        if (m && rank < KK) out[rank] = i;
        cnt += __popc(bal);
        if (cnt >= KK) break;
    }
    if (cnt > KK) cnt = KK;
    for (int j = cnt + lane; j < KK; j += 32) out[j] = -1;
}

// ---------------------------------------------------------------------------
// MLP 67->64->64->128 + ReLU + max over K as register-tiled SGEMM.
// Block = 2 queries = 128 columns, 256 threads.
// Weights transposed in smem -> LDS.128 loads; acc tiles 4x8 (L1/L2), 8x8 (L3).
// smem offsets (floats):
//   sW0t [67][64]  @ 0      (4288)
//   sW1t [64][64]  @ 4288   (4096)
//   sW2t [64][128] @ 8384   (8192)
//   sB0/1/2        @ 16576  (256)
//   sX   [67][128] @ 16832  (8576, reused as L2 output 64x128)
//   sH   [64][128] @ 25408  (8192)
//   sIdx [128] int @ 33600
//   sQ   [2][3]    @ 33728
// ---------------------------------------------------------------------------
__global__ __launch_bounds__(256, 1) void mlp_kernel(
    const float* __restrict__ xyz, const float* __restrict__ pts,
    const float* __restrict__ w0, const float* __restrict__ b0,
    const float* __restrict__ w1, const float* __restrict__ b1,
    const float* __restrict__ w2, const float* __restrict__ b2,
    const float* __restrict__ new_xyz, float* __restrict__ out_pts)
{
    extern __shared__ float sm[];
    float* sW0t = sm;
    float* sW1t = sm + 4288;
    float* sW2t = sm + 8384;
    float* sB0  = sm + 16576;
    float* sB1  = sm + 16640;
    float* sB2  = sm + 16704;
    float* sX   = sm + 16832;
    float* sH   = sm + 25408;
    int*   sIdx = (int*)(sm + 33600);
    float* sQ   = sm + 33728;

    const int tid = threadIdx.x;
    const int qg0 = blockIdx.x * 2;
    const int b = qg0 >> 9;

    // ---- stage weights (transposed), biases, neighbor ids, query coords ----
    for (int i = tid; i < 4288; i += 256) { int o = i / C0, c = i - o * C0; sW0t[c * 64 + o] = w0[i]; }
    for (int i = tid; i < 4096; i += 256) { int o = i >> 6, c = i & 63;     sW1t[c * 64 + o] = w1[i]; }
    for (int i = tid; i < 8192; i += 256) { int o = i >> 6, c = i & 63;     sW2t[c * 128 + o] = w2[i]; }
    if (tid < 64)  sB0[tid] = b0[tid];
    if (tid >= 64 && tid < 128) sB1[tid - 64] = b1[tid - 64];
    if (tid >= 128 && tid < 256) sB2[tid - 128] = b2[tid - 128];
    if (tid < 128) sIdx[tid] = g_nbr[(size_t)qg0 * KK + tid];
    if (tid < 2) {
        int qg = qg0 + tid, s = qg & 511;
        sQ[tid * 3 + 0] = new_xyz[(size_t)b * 3 * SS + s];
        sQ[tid * 3 + 1] = new_xyz[(size_t)b * 3 * SS + SS + s];
        sQ[tid * 3 + 2] = new_xyz[(size_t)b * 3 * SS + 2 * SS + s];
    }
    __syncthreads();

    // ---- gather X [67][128] ----
    {
        const float* xyzB = xyz + (size_t)b * 3 * NP;
        const float* ptsB = pts + (size_t)b * DF * NP;
        int half = tid >> 7;          // 0/1: rows interleaved
        int kk = tid & 127;
        int id = sIdx[kk];
        int gid = (id < 0) ? NP - 1 : id;
        if (tid < 128) {
            int q = kk >> 6;
            float qx = sQ[q * 3], qy = sQ[q * 3 + 1], qz = sQ[q * 3 + 2];
            if (id < 0) { sX[kk] = -qx; sX[128 + kk] = -qy; sX[256 + kk] = -qz; }
            else {
                sX[kk]       = xyzB[id] - qx;
                sX[128 + kk] = xyzB[NP + id] - qy;
                sX[256 + kk] = xyzB[2 * NP + id] - qz;
            }
        }
        const float* pbase = ptsB + (size_t)half * NP + gid;
#pragma unroll 8
        for (int r2 = 0; r2 < 64; r2 += 2)
            sX[(3 + r2 + half) * 128 + kk] = pbase[(size_t)r2 * NP];
    }
    __syncthreads();

    const int kt = tid & 15, k0 = kt * 8;

    // ---- layer 1: 67 -> 64, out sH[o][k] ----
    {
        const int ot = tid >> 4, o0 = ot * 4;
        float acc[4][8];
#pragma unroll
        for (int i = 0; i < 4; i++) {
            float bb = sB0[o0 + i];
#pragma unroll
            for (int j = 0; j < 8; j++) acc[i][j] = bb;
        }
#pragma unroll 4
        for (int c = 0; c < C0; c++) {
            float4 wv = *(const float4*)&sW0t[c * 64 + o0];
            float4 xa = *(const float4*)&sX[c * 128 + k0];
            float4 xb2 = *(const float4*)&sX[c * 128 + k0 + 4];
            float wr[4] = {wv.x, wv.y, wv.z, wv.w};
            float xr[8] = {xa.x, xa.y, xa.z, xa.w, xb2.x, xb2.y, xb2.z, xb2.w};
#pragma unroll
            for (int i = 0; i < 4; i++)
#pragma unroll
                for (int j = 0; j < 8; j++) acc[i][j] = fmaf(wr[i], xr[j], acc[i][j]);
        }
#pragma unroll
        for (int i = 0; i < 4; i++) {
            float4 v0, v1;
            v0.x = fmaxf(acc[i][0], 0.f); v0.y = fmaxf(acc[i][1], 0.f);
            v0.z = fmaxf(acc[i][2], 0.f); v0.w = fmaxf(acc[i][3], 0.f);
            v1.x = fmaxf(acc[i][4], 0.f); v1.y = fmaxf(acc[i][5], 0.f);
            v1.z = fmaxf(acc[i][6], 0.f); v1.w = fmaxf(acc[i][7], 0.f);
            *(float4*)&sH[(o0 + i) * 128 + k0] = v0;
            *(float4*)&sH[(o0 + i) * 128 + k0 + 4] = v1;
        }
    }
    __syncthreads();

    // ---- layer 2: 64 -> 64, in sH, out sX ----
    {
        const int ot = tid >> 4, o0 = ot * 4;
        float acc[4][8];
#pragma unroll
        for (int i = 0; i < 4; i++) {
            float bb = sB1[o0 + i];
#pragma unroll
            for (int j = 0; j < 8; j++) acc[i][j] = bb;
        }
#pragma unroll 4
        for (int c = 0; c < 64; c++) {
            float4 wv = *(const float4*)&sW1t[c * 64 + o0];
            float4 xa = *(const float4*)&sH[c * 128 + k0];
            float4 xb2 = *(const float4*)&sH[c * 128 + k0 + 4];
            float wr[4] = {wv.x, wv.y, wv.z, wv.w};
            float xr[8] = {xa.x, xa.y, xa.z, xa.w, xb2.x, xb2.y, xb2.z, xb2.w};
#pragma unroll
            for (int i = 0; i < 4; i++)
#pragma unroll
                for (int j = 0; j < 8; j++) acc[i][j] = fmaf(wr[i], xr[j], acc[i][j]);
        }
        __syncthreads();   // all sH reads done before sX overwrite
#pragma unroll
        for (int i = 0; i < 4; i++) {
            float4 v0, v1;
            v0.x = fmaxf(acc[i][0], 0.f); v0.y = fmaxf(acc[i][1], 0.f);
            v0.z = fmaxf(acc[i][2], 0.f); v0.w = fmaxf(acc[i][3], 0.f);
            v1.x = fmaxf(acc[i][4], 0.f); v1.y = fmaxf(acc[i][5], 0.f);
            v1.z = fmaxf(acc[i][6], 0.f); v1.w = fmaxf(acc[i][7], 0.f);
            *(float4*)&sX[(o0 + i) * 128 + k0] = v0;
            *(float4*)&sX[(o0 + i) * 128 + k0 + 4] = v1;
        }
    }
    __syncthreads();

    // ---- layer 3: 64 -> 128, in sX, + max over K, write out ----
    {
        const int ot = tid >> 4, o0 = ot * 8;
        float acc[8][8];
#pragma unroll
        for (int i = 0; i < 8; i++) {
            float bb = sB2[o0 + i];
#pragma unroll
            for (int j = 0; j < 8; j++) acc[i][j] = bb;
        }
#pragma unroll 2
        for (int c = 0; c < 64; c++) {
            float4 wa = *(const float4*)&sW2t[c * 128 + o0];
            float4 wb = *(const float4*)&sW2t[c * 128 + o0 + 4];
            float4 xa = *(const float4*)&sX[c * 128 + k0];
            float4 xb2 = *(const float4*)&sX[c * 128 + k0 + 4];
            float wr[8] = {wa.x, wa.y, wa.z, wa.w, wb.x, wb.y, wb.z, wb.w};
            float xr[8] = {xa.x, xa.y, xa.z, xa.w, xb2.x, xb2.y, xb2.z, xb2.w};
#pragma unroll
            for (int i = 0; i < 8; i++)
#pragma unroll
                for (int j = 0; j < 8; j++) acc[i][j] = fmaf(wr[i], xr[j], acc[i][j]);
        }
        // max over this thread's 8 columns, then across the 8 kt of same query
        int q = kt >> 3;
        int qg = qg0 + q, s = qg & 511;
#pragma unroll
        for (int i = 0; i < 8; i++) {
            float m = acc[i][0];
#pragma unroll
            for (int j = 1; j < 8; j++) m = fmaxf(m, acc[i][j]);
#pragma unroll
            for (int d = 1; d < 8; d <<= 1)
                m = fmaxf(m, __shfl_xor_sync(0xffffffffu, m, d));
            m = fmaxf(m, 0.0f);
            if ((kt & 7) == 0)
                out_pts[(size_t)b * 128 * SS + (size_t)(o0 + i) * SS + s] = m;
        }
    }
}

// ---------------------------------------------------------------------------
extern "C" void kernel_launch(void* const* d_in, const int* in_sizes, int n_in,
                              void* d_out, int out_size)
{
    const float* xyz  = (const float*)d_in[0];
    const float* pts  = (const float*)d_in[1];
    const float* attn = (const float*)d_in[2];
    const float* w0   = (const float*)d_in[3];
    const float* b0   = (const float*)d_in[4];
    const float* w1   = (const float*)d_in[5];
    const float* b1   = (const float*)d_in[6];
    const float* w2   = (const float*)d_in[7];
    const float* b2   = (const float*)d_in[8];

    float* out      = (float*)d_out;
    float* out_xyz  = out;                               // [B,3,S]
    float* out_pts  = out + BN * 3 * SS;                 // [B,128,S]
    float* out_attn = out + BN * 3 * SS + BN * 128 * SS; // [B,1,S]

    size_t fps_smem = (size_t)3 * NP * sizeof(float);     // 96 KB
    size_t mlp_smem = (size_t)33736 * sizeof(float);      // ~132 KB

    cudaFuncSetAttribute(fps_kernel, cudaFuncAttributeMaxDynamicSharedMemorySize, (int)fps_smem);
    cudaFuncSetAttribute(mlp_kernel, cudaFuncAttributeMaxDynamicSharedMemorySize, (int)mlp_smem);

    fps_kernel<<<dim3(2, BN), 512, fps_smem>>>(xyz, attn, out_xyz, out_attn);
    ball_kernel<<<BN * SS / 8, 256>>>(xyz, out_xyz);
    mlp_kernel<<<BN * SS / 2, 256, mlp_smem>>>(xyz, pts, w0, b0, w1, b1, w2, b2,
                                               out_xyz, out_pts);
}

// round 3
// speedup vs baseline: 1.5106x; 1.1255x over previous
#include <cuda_runtime.h>

#define BN 8
#define NP 8192
#define SS 512
#define SA 128
#define SNN 384
#define KK 64
#define DF 64
#define C0 67

typedef unsigned long long ull;

__device__ int   g_nbr[BN * SS * KK];
__device__ float g_w0t[C0 * 64];
__device__ float g_w1t[64 * 64];
__device__ float g_w2t[64 * 128];

// ---- packed f32x2 helpers (Blackwell FFMA2 path, PTX-only) ----
__device__ __forceinline__ ull pk2(float lo, float hi) {
    ull r; asm("mov.b64 %0, {%1, %2};" : "=l"(r) : "f"(lo), "f"(hi)); return r;
}
__device__ __forceinline__ void upk2(ull v, float& lo, float& hi) {
    asm("mov.b64 {%0, %1}, %2;" : "=f"(lo), "=f"(hi) : "l"(v));
}
__device__ __forceinline__ ull ffma2(ull a, ull b, ull c) {
    ull d; asm("fma.rn.f32x2 %0, %1, %2, %3;" : "=l"(d) : "l"(a), "l"(b), "l"(c)); return d;
}
__device__ __forceinline__ ull fadd2(ull a, ull b) {
    ull d; asm("add.rn.f32x2 %0, %1, %2;" : "=l"(d) : "l"(a), "l"(b)); return d;
}

// ---------------------------------------------------------------------------
// Weight pre-transpose: w[o][c] -> wT[c][o], once, into device globals.
// ---------------------------------------------------------------------------
__global__ void prep_kernel(const float* __restrict__ w0,
                            const float* __restrict__ w1,
                            const float* __restrict__ w2)
{
    int t = blockIdx.x * 256 + threadIdx.x;
    if (t < 4288) {
        int o = t / C0, c = t - o * C0;
        g_w0t[c * 64 + o] = w0[t];
    } else if (t < 8384) {
        int i = t - 4288; int o = i >> 6, c = i & 63;
        g_w1t[c * 64 + o] = w1[i];
    } else if (t < 16576) {
        int i = t - 8384; int o = i >> 6, c = i & 63;
        g_w2t[c * 128 + o] = w2[i];
    }
}

// ---------------------------------------------------------------------------
// FPS main loop, templated on pairs-per-thread P (2P points per thread).
// Slots are order-preserving => atomicMin(slot) == lowest-original-index
// tie-break among exactly-equal min-distances (the duplicate-zero case is
// collapsed to a single representative at slot M).
// ---------------------------------------------------------------------------
template<int P>
__device__ void fps_loop(const float* cx, const float* cy, const float* cz,
                         int last, int Ksel, int off, int b, int which,
                         int M, int Mr,
                         float* out_xyz, float* out_attn,
                         unsigned* warpmax, int* s_best)
{
    const int tid = threadIdx.x, lane = tid & 31, wid = tid >> 5;
    const int base = tid * 2 * P;

    ull pxu[P], pyu[P], pzu[P], pnu[P];
    float mdlo[P], mdhi[P];
#pragma unroll
    for (int p = 0; p < P; p++) {
        float x0 = cx[base + 2 * p],     y0 = cy[base + 2 * p],     z0 = cz[base + 2 * p];
        float x1 = cx[base + 2 * p + 1], y1 = cy[base + 2 * p + 1], z1 = cz[base + 2 * p + 1];
        pxu[p] = pk2(x0, x1); pyu[p] = pk2(y0, y1); pzu[p] = pk2(z0, z1);
        pnu[p] = pk2(fmaf(z0, z0, fmaf(y0, y0, x0 * x0)),
                     fmaf(z1, z1, fmaf(y1, y1, x1 * x1)));
        mdlo[p] = (base + 2 * p)     < Mr ? 1e10f : -1e30f;
        mdhi[p] = (base + 2 * p + 1) < Mr ? 1e10f : -1e30f;
    }

    const float keep_val = (which == 0) ? 1.0f : 0.0f;
    int parity = 0;
    for (int k = 0;; k++) {
        float lx = cx[last], ly = cy[last], lz = cz[last];
        if (tid == 0) {
            int o = off + k;
            out_xyz[(size_t)b * 3 * SS + o]          = lx;
            out_xyz[(size_t)b * 3 * SS + SS + o]     = ly;
            out_xyz[(size_t)b * 3 * SS + 2 * SS + o] = lz;
            out_attn[(size_t)b * SS + o] = (last < M) ? keep_val : 1.0f - keep_val;
        }
        if (k == Ksel - 1) break;

        float ln = fmaf(lz, lz, fmaf(ly, ly, lx * lx));
        ull lx2 = pk2(-2.0f * lx, -2.0f * lx);
        ull ly2 = pk2(-2.0f * ly, -2.0f * ly);
        ull lz2 = pk2(-2.0f * lz, -2.0f * lz);
        ull lnp = pk2(ln, ln);

        float tmax = -1e30f;
#pragma unroll
        for (int p = 0; p < P; p++) {
            ull e = ffma2(pzu[p], lz2, ffma2(pyu[p], ly2, ffma2(pxu[p], lx2, pnu[p])));
            e = fadd2(e, lnp);
            float elo, ehi; upk2(e, elo, ehi);
            mdlo[p] = fminf(mdlo[p], elo);
            mdhi[p] = fminf(mdhi[p], ehi);
            tmax = fmaxf(tmax, mdlo[p]);
            tmax = fmaxf(tmax, mdhi[p]);
        }
        unsigned tc = __float_as_uint(fmaxf(tmax, 0.0f));
        unsigned wm = __reduce_max_sync(0xffffffffu, tc);
        if (lane == 0) warpmax[wid] = wm;
        __syncthreads();

        if (tid == 0) s_best[parity ^ 1] = 0x7fffffff;
        unsigned W = warpmax[0];
#pragma unroll
        for (int w = 1; w < 16; w++) W = max(W, warpmax[w]);

        if (tc == W) {
            float Wf = __uint_as_float(W);
            int bi = 0x7fffffff;
#pragma unroll
            for (int p = 0; p < P; p++) {
                bi = min(bi, (mdlo[p] == Wf) ? (base + 2 * p)     : 0x7fffffff);
                bi = min(bi, (mdhi[p] == Wf) ? (base + 2 * p + 1) : 0x7fffffff);
            }
            if (bi != 0x7fffffff) atomicMin(&s_best[parity], bi);
        }
        __syncthreads();
        last = s_best[parity];
        parity ^= 1;
    }
}

// ---------------------------------------------------------------------------
// FPS: one block per (batch, {attn,none}). Compacts to kept points (order-
// preserving) + one zero-representative, then runs the packed loop.
// ---------------------------------------------------------------------------
__global__ __launch_bounds__(512, 1) void fps_kernel(
    const float* __restrict__ xyz, const float* __restrict__ attn,
    float* __restrict__ out_xyz, float* __restrict__ out_attn)
{
    extern __shared__ float sm[];
    float* cx = sm;
    float* cy = sm + NP;
    float* cz = sm + 2 * NP;
    __shared__ int s_wsum[16];
    __shared__ int s_woff[16];
    __shared__ unsigned warpmax[16];
    __shared__ int s_best[2];
    __shared__ int s_zero;
    __shared__ int s_M;

    const int tid = threadIdx.x;
    const int lane = tid & 31, wid = tid >> 5;
    const int b = blockIdx.y;
    const int which = blockIdx.x;
    const int Ksel = (which == 0) ? SA : SNN;
    const int off  = (which == 0) ? 0 : SA;

    const float* xb = xyz + (size_t)b * 3 * NP;
    const float* ab = attn + (size_t)b * NP;

    if (tid == 0) { s_zero = 0x7fffffff; s_best[0] = 0x7fffffff; s_best[1] = 0x7fffffff; }

    // load 16 consecutive points per thread (coalesced 128B per warp slice)
    const int ibase = tid * 16;
    float xv[16], yv[16], zv[16];
    unsigned km = 0;
    int zm = 0x7fffffff;
#pragma unroll
    for (int j4 = 0; j4 < 4; j4++) {
        float4 a4 = *(const float4*)&ab[ibase + j4 * 4];
        float4 x4 = *(const float4*)&xb[ibase + j4 * 4];
        float4 y4 = *(const float4*)&xb[NP + ibase + j4 * 4];
        float4 z4 = *(const float4*)&xb[2 * NP + ibase + j4 * 4];
        float aa[4] = {a4.x, a4.y, a4.z, a4.w};
        float xx[4] = {x4.x, x4.y, x4.z, x4.w};
        float yy[4] = {y4.x, y4.y, y4.z, y4.w};
        float zz[4] = {z4.x, z4.y, z4.z, z4.w};
#pragma unroll
        for (int q = 0; q < 4; q++) {
            int j = j4 * 4 + q;
            float f = (which == 0) ? aa[q] : 1.0f - aa[q];
            xv[j] = xx[q]; yv[j] = yy[q]; zv[j] = zz[q];
            if (f != 0.0f) km |= 1u << j;
            else zm = min(zm, ibase + j);
        }
    }
    int cnt = __popc(km);

    // block exclusive scan over per-thread counts (order-preserving)
    int incl = cnt;
#pragma unroll
    for (int d = 1; d < 32; d <<= 1) {
        int v = __shfl_up_sync(0xffffffffu, incl, d);
        if (lane >= d) incl += v;
    }
    if (lane == 31) s_wsum[wid] = incl;
    if (zm != 0x7fffffff) atomicMin(&s_zero, zm);
    __syncthreads();
    if (tid < 16) {
        int v = s_wsum[tid];
        int iv = v;
#pragma unroll
        for (int d = 1; d < 16; d <<= 1) {
            int t = __shfl_up_sync(0x0000ffffu, iv, d);
            if (tid >= d) iv += t;
        }
        s_woff[tid] = iv - v;
        if (tid == 15) s_M = iv;
    }
    __syncthreads();

    int pos = s_woff[wid] + incl - cnt;
#pragma unroll
    for (int j = 0; j < 16; j++) {
        if ((km >> j) & 1u) {
            cx[pos] = xv[j]; cy[pos] = yv[j]; cz[pos] = zv[j];
            pos++;
        }
    }
    __syncthreads();

    const int M = s_M;
    int Mr = M;
    if (s_zero != 0x7fffffff) {
        if (tid == 0) { cx[M] = 0.0f; cy[M] = 0.0f; cz[M] = 0.0f; }
        Mr = M + 1;
    }
    int P = (Mr + 1023) >> 10;
    if (P < 1) P = 1;
    int Npad = P << 10;
    for (int i = Mr + tid; i < Npad; i += 512) { cx[i] = 0.0f; cy[i] = 0.0f; cz[i] = 0.0f; }
    __syncthreads();

    // initial selection is original index 0: kept => slot 0, else the zero rep.
    float a0 = ab[0];
    float f0 = (which == 0) ? a0 : 1.0f - a0;
    int last = (f0 != 0.0f) ? 0 : M;

    switch (P) {
        case 1: fps_loop<1>(cx, cy, cz, last, Ksel, off, b, which, M, Mr, out_xyz, out_attn, warpmax, s_best); break;
        case 2: fps_loop<2>(cx, cy, cz, last, Ksel, off, b, which, M, Mr, out_xyz, out_attn, warpmax, s_best); break;
        case 3: fps_loop<3>(cx, cy, cz, last, Ksel, off, b, which, M, Mr, out_xyz, out_attn, warpmax, s_best); break;
        case 4: fps_loop<4>(cx, cy, cz, last, Ksel, off, b, which, M, Mr, out_xyz, out_attn, warpmax, s_best); break;
        case 5: fps_loop<5>(cx, cy, cz, last, Ksel, off, b, which, M, Mr, out_xyz, out_attn, warpmax, s_best); break;
        case 6: fps_loop<6>(cx, cy, cz, last, Ksel, off, b, which, M, Mr, out_xyz, out_attn, warpmax, s_best); break;
        case 7: fps_loop<7>(cx, cy, cz, last, Ksel, off, b, which, M, Mr, out_xyz, out_attn, warpmax, s_best); break;
        default: fps_loop<8>(cx, cy, cz, last, Ksel, off, b, which, M, Mr, out_xyz, out_attn, warpmax, s_best); break;
    }
}

// ---------------------------------------------------------------------------
// Ball query: one warp per query, first KK in index order, pad -1.
// ---------------------------------------------------------------------------
__global__ __launch_bounds__(256, 1) void ball_kernel(
    const float* __restrict__ xyz, const float* __restrict__ new_xyz)
{
    int w = blockIdx.x * 8 + (threadIdx.x >> 5);
    int lane = threadIdx.x & 31;
    int b = w >> 9, s = w & 511;
    const float R2 = (float)(0.4 * 0.4);

    float qx = new_xyz[(size_t)b * 3 * SS + s];
    float qy = new_xyz[(size_t)b * 3 * SS + SS + s];
    float qz = new_xyz[(size_t)b * 3 * SS + 2 * SS + s];
    const float* xb = xyz + (size_t)b * 3 * NP;
    int* out = g_nbr + (size_t)w * KK;

    int cnt = 0;
    for (int base = 0; base < NP; base += 32) {
        int i = base + lane;
        float dx = xb[i] - qx, dy = xb[NP + i] - qy, dz = xb[2 * NP + i] - qz;
        float d2 = fmaf(dz, dz, fmaf(dy, dy, dx * dx));
        bool m = d2 < R2;
        unsigned bal = __ballot_sync(0xffffffffu, m);
        int rank = cnt + __popc(bal & ((1u << lane) - 1u));
        if (m && rank < KK) out[rank] = i;
        cnt += __popc(bal);
        if (cnt >= KK) break;
    }
    if (cnt > KK) cnt = KK;
    for (int j = cnt + lane; j < KK; j += 32) out[j] = -1;
}

// ---------------------------------------------------------------------------
// MLP 67->64->64->128 + ReLU + max over K as register-tiled SGEMM.
// Block = 2 queries = 128 columns, 256 threads. Weights pre-transposed in
// gmem -> conflict-free coalesced smem staging.
// ---------------------------------------------------------------------------
__global__ __launch_bounds__(256, 1) void mlp_kernel(
    const float* __restrict__ xyz, const float* __restrict__ pts,
    const float* __restrict__ b0, const float* __restrict__ b1,
    const float* __restrict__ b2,
    const float* __restrict__ new_xyz, float* __restrict__ out_pts)
{
    extern __shared__ float sm[];
    float* sW0t = sm;
    float* sW1t = sm + 4288;
    float* sW2t = sm + 8384;
    float* sB0  = sm + 16576;
    float* sB1  = sm + 16640;
    float* sB2  = sm + 16704;
    float* sX   = sm + 16832;
    float* sH   = sm + 25408;
    int*   sIdx = (int*)(sm + 33600);
    float* sQ   = sm + 33728;

    const int tid = threadIdx.x;
    const int qg0 = blockIdx.x * 2;
    const int b = qg0 >> 9;

    for (int i = tid; i < 4288; i += 256) sW0t[i] = g_w0t[i];
    for (int i = tid; i < 4096; i += 256) sW1t[i] = g_w1t[i];
    for (int i = tid; i < 8192; i += 256) sW2t[i] = g_w2t[i];
    if (tid < 64)  sB0[tid] = b0[tid];
    if (tid >= 64 && tid < 128) sB1[tid - 64] = b1[tid - 64];
    if (tid >= 128 && tid < 256) sB2[tid - 128] = b2[tid - 128];
    if (tid < 128) sIdx[tid] = g_nbr[(size_t)qg0 * KK + tid];
    if (tid < 2) {
        int qg = qg0 + tid, s = qg & 511;
        sQ[tid * 3 + 0] = new_xyz[(size_t)b * 3 * SS + s];
        sQ[tid * 3 + 1] = new_xyz[(size_t)b * 3 * SS + SS + s];
        sQ[tid * 3 + 2] = new_xyz[(size_t)b * 3 * SS + 2 * SS + s];
    }
    __syncthreads();

    // ---- gather X [67][128] ----
    {
        const float* xyzB = xyz + (size_t)b * 3 * NP;
        const float* ptsB = pts + (size_t)b * DF * NP;
        int half = tid >> 7;
        int kk = tid & 127;
        int id = sIdx[kk];
        int gid = (id < 0) ? NP - 1 : id;
        if (tid < 128) {
            int q = kk >> 6;
            float qx = sQ[q * 3], qy = sQ[q * 3 + 1], qz = sQ[q * 3 + 2];
            if (id < 0) { sX[kk] = -qx; sX[128 + kk] = -qy; sX[256 + kk] = -qz; }
            else {
                sX[kk]       = xyzB[id] - qx;
                sX[128 + kk] = xyzB[NP + id] - qy;
                sX[256 + kk] = xyzB[2 * NP + id] - qz;
            }
        }
        const float* pbase = ptsB + (size_t)half * NP + gid;
#pragma unroll 8
        for (int r2 = 0; r2 < 64; r2 += 2)
            sX[(3 + r2 + half) * 128 + kk] = pbase[(size_t)r2 * NP];
    }
    __syncthreads();

    const int kt = tid & 15, k0 = kt * 8;

    // ---- layer 1: 67 -> 64 ----
    {
        const int ot = tid >> 4, o0 = ot * 4;
        float acc[4][8];
#pragma unroll
        for (int i = 0; i < 4; i++) {
            float bb = sB0[o0 + i];
#pragma unroll
            for (int j = 0; j < 8; j++) acc[i][j] = bb;
        }
#pragma unroll 4
        for (int c = 0; c < C0; c++) {
            float4 wv = *(const float4*)&sW0t[c * 64 + o0];
            float4 xa = *(const float4*)&sX[c * 128 + k0];
            float4 xb2 = *(const float4*)&sX[c * 128 + k0 + 4];
            float wr[4] = {wv.x, wv.y, wv.z, wv.w};
            float xr[8] = {xa.x, xa.y, xa.z, xa.w, xb2.x, xb2.y, xb2.z, xb2.w};
#pragma unroll
            for (int i = 0; i < 4; i++)
#pragma unroll
                for (int j = 0; j < 8; j++) acc[i][j] = fmaf(wr[i], xr[j], acc[i][j]);
        }
#pragma unroll
        for (int i = 0; i < 4; i++) {
            float4 v0, v1;
            v0.x = fmaxf(acc[i][0], 0.f); v0.y = fmaxf(acc[i][1], 0.f);
            v0.z = fmaxf(acc[i][2], 0.f); v0.w = fmaxf(acc[i][3], 0.f);
            v1.x = fmaxf(acc[i][4], 0.f); v1.y = fmaxf(acc[i][5], 0.f);
            v1.z = fmaxf(acc[i][6], 0.f); v1.w = fmaxf(acc[i][7], 0.f);
            *(float4*)&sH[(o0 + i) * 128 + k0] = v0;
            *(float4*)&sH[(o0 + i) * 128 + k0 + 4] = v1;
        }
    }
    __syncthreads();

    // ---- layer 2: 64 -> 64 (sH -> sX) ----
    {
        const int ot = tid >> 4, o0 = ot * 4;
        float acc[4][8];
#pragma unroll
        for (int i = 0; i < 4; i++) {
            float bb = sB1[o0 + i];
#pragma unroll
            for (int j = 0; j < 8; j++) acc[i][j] = bb;
        }
#pragma unroll 4
        for (int c = 0; c < 64; c++) {
            float4 wv = *(const float4*)&sW1t[c * 64 + o0];
            float4 xa = *(const float4*)&sH[c * 128 + k0];
            float4 xb2 = *(const float4*)&sH[c * 128 + k0 + 4];
            float wr[4] = {wv.x, wv.y, wv.z, wv.w};
            float xr[8] = {xa.x, xa.y, xa.z, xa.w, xb2.x, xb2.y, xb2.z, xb2.w};
#pragma unroll
            for (int i = 0; i < 4; i++)
#pragma unroll
                for (int j = 0; j < 8; j++) acc[i][j] = fmaf(wr[i], xr[j], acc[i][j]);
        }
        __syncthreads();
#pragma unroll
        for (int i = 0; i < 4; i++) {
            float4 v0, v1;
            v0.x = fmaxf(acc[i][0], 0.f); v0.y = fmaxf(acc[i][1], 0.f);
            v0.z = fmaxf(acc[i][2], 0.f); v0.w = fmaxf(acc[i][3], 0.f);
            v1.x = fmaxf(acc[i][4], 0.f); v1.y = fmaxf(acc[i][5], 0.f);
            v1.z = fmaxf(acc[i][6], 0.f); v1.w = fmaxf(acc[i][7], 0.f);
            *(float4*)&sX[(o0 + i) * 128 + k0] = v0;
            *(float4*)&sX[(o0 + i) * 128 + k0 + 4] = v1;
        }
    }
    __syncthreads();

    // ---- layer 3: 64 -> 128 + max over K ----
    {
        const int ot = tid >> 4, o0 = ot * 8;
        float acc[8][8];
#pragma unroll
        for (int i = 0; i < 8; i++) {
            float bb = sB2[o0 + i];
#pragma unroll
            for (int j = 0; j < 8; j++) acc[i][j] = bb;
        }
#pragma unroll 2
        for (int c = 0; c < 64; c++) {
            float4 wa = *(const float4*)&sW2t[c * 128 + o0];
            float4 wb = *(const float4*)&sW2t[c * 128 + o0 + 4];
            float4 xa = *(const float4*)&sX[c * 128 + k0];
            float4 xb2 = *(const float4*)&sX[c * 128 + k0 + 4];
            float wr[8] = {wa.x, wa.y, wa.z, wa.w, wb.x, wb.y, wb.z, wb.w};
            float xr[8] = {xa.x, xa.y, xa.z, xa.w, xb2.x, xb2.y, xb2.z, xb2.w};
#pragma unroll
            for (int i = 0; i < 8; i++)
#pragma unroll
                for (int j = 0; j < 8; j++) acc[i][j] = fmaf(wr[i], xr[j], acc[i][j]);
        }
        int q = kt >> 3;
        int qg = qg0 + q, s = qg & 511;
#pragma unroll
        for (int i = 0; i < 8; i++) {
            float m = acc[i][0];
#pragma unroll
            for (int j = 1; j < 8; j++) m = fmaxf(m, acc[i][j]);
#pragma unroll
            for (int d = 1; d < 8; d <<= 1)
                m = fmaxf(m, __shfl_xor_sync(0xffffffffu, m, d));
            m = fmaxf(m, 0.0f);
            if ((kt & 7) == 0)
                out_pts[(size_t)b * 128 * SS + (size_t)(o0 + i) * SS + s] = m;
        }
    }
}

// ---------------------------------------------------------------------------
extern "C" void kernel_launch(void* const* d_in, const int* in_sizes, int n_in,
                              void* d_out, int out_size)
{
    const float* xyz  = (const float*)d_in[0];
    const float* pts  = (const float*)d_in[1];
    const float* attn = (const float*)d_in[2];
    const float* w0   = (const float*)d_in[3];
    const float* b0   = (const float*)d_in[4];
    const float* w1   = (const float*)d_in[5];
    const float* b1   = (const float*)d_in[6];
    const float* w2   = (const float*)d_in[7];
    const float* b2   = (const float*)d_in[8];

    float* out      = (float*)d_out;
    float* out_xyz  = out;                               // [B,3,S]
    float* out_pts  = out + BN * 3 * SS;                 // [B,128,S]
    float* out_attn = out + BN * 3 * SS + BN * 128 * SS; // [B,1,S]

    size_t fps_smem = (size_t)3 * NP * sizeof(float);     // 96 KB
    size_t mlp_smem = (size_t)33736 * sizeof(float);      // ~132 KB

    cudaFuncSetAttribute(fps_kernel, cudaFuncAttributeMaxDynamicSharedMemorySize, (int)fps_smem);
    cudaFuncSetAttribute(mlp_kernel, cudaFuncAttributeMaxDynamicSharedMemorySize, (int)mlp_smem);

    prep_kernel<<<65, 256>>>(w0, w1, w2);
    fps_kernel<<<dim3(2, BN), 512, fps_smem>>>(xyz, attn, out_xyz, out_attn);
    ball_kernel<<<BN * SS / 8, 256>>>(xyz, out_xyz);
    mlp_kernel<<<BN * SS / 2, 256, mlp_smem>>>(xyz, pts, b0, b1, b2, out_xyz, out_pts);
}

// round 4
// speedup vs baseline: 1.5439x; 1.0220x over previous
#include <cuda_runtime.h>

#define BN 8
#define NP 8192
#define SS 512
#define SA 128
#define SNN 384
#define KK 64
#define DF 64
#define C0 67

typedef unsigned long long ull;

__device__ int   g_nbr[BN * SS * KK];
__device__ float g_w0t[C0 * 64];
__device__ float g_w1t[64 * 64];
__device__ float g_w2t[64 * 128];

// ---- packed f32x2 helpers (Blackwell FFMA2 path, PTX-only) ----
__device__ __forceinline__ ull pk2(float lo, float hi) {
    ull r; asm("mov.b64 %0, {%1, %2};" : "=l"(r) : "f"(lo), "f"(hi)); return r;
}
__device__ __forceinline__ void upk2(ull v, float& lo, float& hi) {
    asm("mov.b64 {%0, %1}, %2;" : "=f"(lo), "=f"(hi) : "l"(v));
}
__device__ __forceinline__ ull ffma2(ull a, ull b, ull c) {
    ull d; asm("fma.rn.f32x2 %0, %1, %2, %3;" : "=l"(d) : "l"(a), "l"(b), "l"(c)); return d;
}
__device__ __forceinline__ ull fadd2(ull a, ull b) {
    ull d; asm("add.rn.f32x2 %0, %1, %2;" : "=l"(d) : "l"(a), "l"(b)); return d;
}

// ---------------------------------------------------------------------------
// Weight pre-transpose: w[o][c] -> wT[c][o], once, into device globals.
// ---------------------------------------------------------------------------
__global__ void prep_kernel(const float* __restrict__ w0,
                            const float* __restrict__ w1,
                            const float* __restrict__ w2)
{
    int t = blockIdx.x * 256 + threadIdx.x;
    if (t < 4288) {
        int o = t / C0, c = t - o * C0;
        g_w0t[c * 64 + o] = w0[t];
    } else if (t < 8384) {
        int i = t - 4288; int o = i >> 6, c = i & 63;
        g_w1t[c * 64 + o] = w1[i];
    } else if (t < 16576) {
        int i = t - 8384; int o = i >> 6, c = i & 63;
        g_w2t[c * 128 + o] = w2[i];
    }
}

// ---------------------------------------------------------------------------
// FPS main loop: ONE barrier per iteration.
// Per-warp (max, lowest-matching-index) -> u64 key (wm<<32)|(INF-idx);
// block winner = 16-way max over double-buffered smem keys, computed
// redundantly by every thread after a single __syncthreads.
// Slot order is original-index order => lowest slot == lowest original index
// among exact ties (zero-duplicates collapsed to one representative slot M).
// ---------------------------------------------------------------------------
template<int P>
__device__ __forceinline__ void fps_loop(
    const float* cx, const float* cy, const float* cz,
    int last, int Ksel, int off, int b, int which,
    int M, int Mr, float* out_xyz, float* out_attn, ull* s_key)
{
    const int tid = threadIdx.x, lane = tid & 31, wid = tid >> 5;
    const int base = tid * 2 * P;

    ull pxu[P], pyu[P], pzu[P], pnu[P];
    float mdlo[P], mdhi[P];
#pragma unroll
    for (int p = 0; p < P; p++) {
        float x0 = cx[base + 2 * p],     y0 = cy[base + 2 * p],     z0 = cz[base + 2 * p];
        float x1 = cx[base + 2 * p + 1], y1 = cy[base + 2 * p + 1], z1 = cz[base + 2 * p + 1];
        pxu[p] = pk2(x0, x1); pyu[p] = pk2(y0, y1); pzu[p] = pk2(z0, z1);
        pnu[p] = pk2(fmaf(z0, z0, fmaf(y0, y0, x0 * x0)),
                     fmaf(z1, z1, fmaf(y1, y1, x1 * x1)));
        mdlo[p] = (base + 2 * p)     < Mr ? 1e10f : -1e30f;
        mdhi[p] = (base + 2 * p + 1) < Mr ? 1e10f : -1e30f;
    }

    const float keep_val = (which == 0) ? 1.0f : 0.0f;
    int par = 0;
    for (int k = 0;; k++) {
        float lx = cx[last], ly = cy[last], lz = cz[last];
        if (tid == 0) {
            int o = off + k;
            out_xyz[(size_t)b * 3 * SS + o]          = lx;
            out_xyz[(size_t)b * 3 * SS + SS + o]     = ly;
            out_xyz[(size_t)b * 3 * SS + 2 * SS + o] = lz;
            out_attn[(size_t)b * SS + o] = (last < M) ? keep_val : 1.0f - keep_val;
        }
        if (k == Ksel - 1) break;

        float ln = fmaf(lz, lz, fmaf(ly, ly, lx * lx));
        ull lx2 = pk2(-2.0f * lx, -2.0f * lx);
        ull ly2 = pk2(-2.0f * ly, -2.0f * ly);
        ull lz2 = pk2(-2.0f * lz, -2.0f * lz);
        ull lnp = pk2(ln, ln);

        float tmax = -1e30f;
#pragma unroll
        for (int p = 0; p < P; p++) {
            ull e = ffma2(pzu[p], lz2, ffma2(pyu[p], ly2, ffma2(pxu[p], lx2, pnu[p])));
            e = fadd2(e, lnp);
            float elo, ehi; upk2(e, elo, ehi);
            mdlo[p] = fminf(mdlo[p], elo);
            mdhi[p] = fminf(mdhi[p], ehi);
            tmax = fmaxf(tmax, fmaxf(mdlo[p], mdhi[p]));
        }
        unsigned tc = __float_as_uint(fmaxf(tmax, 0.0f));
        unsigned wm = __reduce_max_sync(0xffffffffu, tc);
        float Wf = __uint_as_float(wm);
        int mybi = 0x7fffffff;
#pragma unroll
        for (int p = 0; p < P; p++) {
            mybi = min(mybi, (mdlo[p] == Wf) ? (base + 2 * p)     : 0x7fffffff);
            mybi = min(mybi, (mdhi[p] == Wf) ? (base + 2 * p + 1) : 0x7fffffff);
        }
        int wbi = __reduce_min_sync(0xffffffffu, mybi);
        if (lane == 0)
            s_key[par * 16 + wid] = ((ull)wm << 32) | (unsigned)(0x7fffffff - wbi);
        __syncthreads();

        ull kb = s_key[par * 16];
#pragma unroll
        for (int w = 1; w < 16; w++) {
            ull v = s_key[par * 16 + w];
            kb = (v > kb) ? v : kb;
        }
        last = 0x7fffffff - (int)(unsigned)(kb & 0xffffffffu);
        par ^= 1;
    }
}

// ---------------------------------------------------------------------------
// FPS: one block per (batch, {attn,none}). Compacts to kept points (order-
// preserving) + one zero-representative, then runs the packed loop.
// ---------------------------------------------------------------------------
__global__ __launch_bounds__(512, 1) void fps_kernel(
    const float* __restrict__ xyz, const float* __restrict__ attn,
    float* __restrict__ out_xyz, float* __restrict__ out_attn)
{
    extern __shared__ float sm[];
    float* cx = sm;
    float* cy = sm + NP;
    float* cz = sm + 2 * NP;
    __shared__ int s_wsum[16];
    __shared__ int s_woff[16];
    __shared__ ull s_key[32];
    __shared__ int s_zero;
    __shared__ int s_M;

    const int tid = threadIdx.x;
    const int lane = tid & 31, wid = tid >> 5;
    const int b = blockIdx.y;
    const int which = blockIdx.x;
    const int Ksel = (which == 0) ? SA : SNN;
    const int off  = (which == 0) ? 0 : SA;

    const float* xb = xyz + (size_t)b * 3 * NP;
    const float* ab = attn + (size_t)b * NP;

    if (tid == 0) s_zero = 0x7fffffff;

    const int ibase = tid * 16;
    float xv[16], yv[16], zv[16];
    unsigned km = 0;
    int zm = 0x7fffffff;
#pragma unroll
    for (int j4 = 0; j4 < 4; j4++) {
        float4 a4 = *(const float4*)&ab[ibase + j4 * 4];
        float4 x4 = *(const float4*)&xb[ibase + j4 * 4];
        float4 y4 = *(const float4*)&xb[NP + ibase + j4 * 4];
        float4 z4 = *(const float4*)&xb[2 * NP + ibase + j4 * 4];
        float aa[4] = {a4.x, a4.y, a4.z, a4.w};
        float xx[4] = {x4.x, x4.y, x4.z, x4.w};
        float yy[4] = {y4.x, y4.y, y4.z, y4.w};
        float zz[4] = {z4.x, z4.y, z4.z, z4.w};
#pragma unroll
        for (int q = 0; q < 4; q++) {
            int j = j4 * 4 + q;
            float f = (which == 0) ? aa[q] : 1.0f - aa[q];
            xv[j] = xx[q]; yv[j] = yy[q]; zv[j] = zz[q];
            if (f != 0.0f) km |= 1u << j;
            else zm = min(zm, ibase + j);
        }
    }
    int cnt = __popc(km);

    int incl = cnt;
#pragma unroll
    for (int d = 1; d < 32; d <<= 1) {
        int v = __shfl_up_sync(0xffffffffu, incl, d);
        if (lane >= d) incl += v;
    }
    if (lane == 31) s_wsum[wid] = incl;
    if (zm != 0x7fffffff) atomicMin(&s_zero, zm);
    __syncthreads();
    if (tid < 16) {
        int v = s_wsum[tid];
        int iv = v;
#pragma unroll
        for (int d = 1; d < 16; d <<= 1) {
            int t = __shfl_up_sync(0x0000ffffu, iv, d);
            if (tid >= d) iv += t;
        }
        s_woff[tid] = iv - v;
        if (tid == 15) s_M = iv;
    }
    __syncthreads();

    int pos = s_woff[wid] + incl - cnt;
#pragma unroll
    for (int j = 0; j < 16; j++) {
        if ((km >> j) & 1u) {
            cx[pos] = xv[j]; cy[pos] = yv[j]; cz[pos] = zv[j];
            pos++;
        }
    }
    __syncthreads();

    const int M = s_M;
    int Mr = M;
    if (s_zero != 0x7fffffff) {
        if (tid == 0) { cx[M] = 0.0f; cy[M] = 0.0f; cz[M] = 0.0f; }
        Mr = M + 1;
    }
    int P = (Mr + 1023) >> 10;
    if (P < 1) P = 1;
    int Npad = P << 10;
    for (int i = Mr + tid; i < Npad; i += 512) { cx[i] = 0.0f; cy[i] = 0.0f; cz[i] = 0.0f; }
    __syncthreads();

    float a0 = ab[0];
    float f0 = (which == 0) ? a0 : 1.0f - a0;
    int last = (f0 != 0.0f) ? 0 : M;

    switch (P) {
        case 1: fps_loop<1>(cx, cy, cz, last, Ksel, off, b, which, M, Mr, out_xyz, out_attn, s_key); break;
        case 2: fps_loop<2>(cx, cy, cz, last, Ksel, off, b, which, M, Mr, out_xyz, out_attn, s_key); break;
        case 3: fps_loop<3>(cx, cy, cz, last, Ksel, off, b, which, M, Mr, out_xyz, out_attn, s_key); break;
        case 4: fps_loop<4>(cx, cy, cz, last, Ksel, off, b, which, M, Mr, out_xyz, out_attn, s_key); break;
        case 5: fps_loop<5>(cx, cy, cz, last, Ksel, off, b, which, M, Mr, out_xyz, out_attn, s_key); break;
        case 6: fps_loop<6>(cx, cy, cz, last, Ksel, off, b, which, M, Mr, out_xyz, out_attn, s_key); break;
        case 7: fps_loop<7>(cx, cy, cz, last, Ksel, off, b, which, M, Mr, out_xyz, out_attn, s_key); break;
        default: fps_loop<8>(cx, cy, cz, last, Ksel, off, b, which, M, Mr, out_xyz, out_attn, s_key); break;
    }
}

// ---------------------------------------------------------------------------
// Ball query: one warp per query, first KK in index order, pad -1.
// ---------------------------------------------------------------------------
__global__ __launch_bounds__(256, 1) void ball_kernel(
    const float* __restrict__ xyz, const float* __restrict__ new_xyz)
{
    int w = blockIdx.x * 8 + (threadIdx.x >> 5);
    int lane = threadIdx.x & 31;
    int b = w >> 9, s = w & 511;
    const float R2 = (float)(0.4 * 0.4);

    float qx = new_xyz[(size_t)b * 3 * SS + s];
    float qy = new_xyz[(size_t)b * 3 * SS + SS + s];
    float qz = new_xyz[(size_t)b * 3 * SS + 2 * SS + s];
    const float* xb = xyz + (size_t)b * 3 * NP;
    int* out = g_nbr + (size_t)w * KK;

    int cnt = 0;
    for (int base = 0; base < NP; base += 32) {
        int i = base + lane;
        float dx = xb[i] - qx, dy = xb[NP + i] - qy, dz = xb[2 * NP + i] - qz;
        float d2 = fmaf(dz, dz, fmaf(dy, dy, dx * dx));
        bool m = d2 < R2;
        unsigned bal = __ballot_sync(0xffffffffu, m);
        int rank = cnt + __popc(bal & ((1u << lane) - 1u));
        if (m && rank < KK) out[rank] = i;
        cnt += __popc(bal);
        if (cnt >= KK) break;
    }
    if (cnt > KK) cnt = KK;
    for (int j = cnt + lane; j < KK; j += 32) out[j] = -1;
}

// ---------------------------------------------------------------------------
// MLP 67->64->64->128 + ReLU + max over K as register-tiled SGEMM.
// Block = 2 queries = 128 columns, 256 threads, 2 blocks/SM.
// Weights read via __ldg from pre-transposed gmem (warp-broadcast, L1-hot)
// => smem holds only activations (69KB) => occupancy 2x.
// smem (floats): sB0 @0, sB1 @64, sB2 @128, sX @256 (8576),
//                sH @8832 (8192), sIdx @17024, sQ @17152
// ---------------------------------------------------------------------------
__global__ __launch_bounds__(256, 2) void mlp_kernel(
    const float* __restrict__ xyz, const float* __restrict__ pts,
    const float* __restrict__ b0, const float* __restrict__ b1,
    const float* __restrict__ b2,
    const float* __restrict__ new_xyz, float* __restrict__ out_pts)
{
    extern __shared__ float sm[];
    float* sB0  = sm;
    float* sB1  = sm + 64;
    float* sB2  = sm + 128;
    float* sX   = sm + 256;
    float* sH   = sm + 8832;
    int*   sIdx = (int*)(sm + 17024);
    float* sQ   = sm + 17152;

    const int tid = threadIdx.x;
    const int qg0 = blockIdx.x * 2;
    const int b = qg0 >> 9;

    if (tid < 64)  sB0[tid] = b0[tid];
    if (tid >= 64 && tid < 128) sB1[tid - 64] = b1[tid - 64];
    if (tid >= 128 && tid < 256) sB2[tid - 128] = b2[tid - 128];
    if (tid < 128) sIdx[tid] = g_nbr[(size_t)qg0 * KK + tid];
    if (tid < 2) {
        int qg = qg0 + tid, s = qg & 511;
        sQ[tid * 3 + 0] = new_xyz[(size_t)b * 3 * SS + s];
        sQ[tid * 3 + 1] = new_xyz[(size_t)b * 3 * SS + SS + s];
        sQ[tid * 3 + 2] = new_xyz[(size_t)b * 3 * SS + 2 * SS + s];
    }
    __syncthreads();

    // ---- gather X [67][128] ----
    {
        const float* xyzB = xyz + (size_t)b * 3 * NP;
        const float* ptsB = pts + (size_t)b * DF * NP;
        int half = tid >> 7;
        int kk = tid & 127;
        int id = sIdx[kk];
        int gid = (id < 0) ? NP - 1 : id;
        if (tid < 128) {
            int q = kk >> 6;
            float qx = sQ[q * 3], qy = sQ[q * 3 + 1], qz = sQ[q * 3 + 2];
            if (id < 0) { sX[kk] = -qx; sX[128 + kk] = -qy; sX[256 + kk] = -qz; }
            else {
                sX[kk]       = xyzB[id] - qx;
                sX[128 + kk] = xyzB[NP + id] - qy;
                sX[256 + kk] = xyzB[2 * NP + id] - qz;
            }
        }
        const float* pbase = ptsB + (size_t)half * NP + gid;
#pragma unroll 8
        for (int r2 = 0; r2 < 64; r2 += 2)
            sX[(3 + r2 + half) * 128 + kk] = pbase[(size_t)r2 * NP];
    }
    __syncthreads();

    const int kt = tid & 15, k0 = kt * 8;

    // ---- layer 1: 67 -> 64 ----
    {
        const int ot = tid >> 4, o0 = ot * 4;
        float acc[4][8];
#pragma unroll
        for (int i = 0; i < 4; i++) {
            float bb = sB0[o0 + i];
#pragma unroll
            for (int j = 0; j < 8; j++) acc[i][j] = bb;
        }
#pragma unroll 4
        for (int c = 0; c < C0; c++) {
            float4 wv = __ldg((const float4*)&g_w0t[c * 64 + o0]);
            float4 xa = *(const float4*)&sX[c * 128 + k0];
            float4 xb2 = *(const float4*)&sX[c * 128 + k0 + 4];
            float wr[4] = {wv.x, wv.y, wv.z, wv.w};
            float xr[8] = {xa.x, xa.y, xa.z, xa.w, xb2.x, xb2.y, xb2.z, xb2.w};
#pragma unroll
            for (int i = 0; i < 4; i++)
#pragma unroll
                for (int j = 0; j < 8; j++) acc[i][j] = fmaf(wr[i], xr[j], acc[i][j]);
        }
#pragma unroll
        for (int i = 0; i < 4; i++) {
            float4 v0, v1;
            v0.x = fmaxf(acc[i][0], 0.f); v0.y = fmaxf(acc[i][1], 0.f);
            v0.z = fmaxf(acc[i][2], 0.f); v0.w = fmaxf(acc[i][3], 0.f);
            v1.x = fmaxf(acc[i][4], 0.f); v1.y = fmaxf(acc[i][5], 0.f);
            v1.z = fmaxf(acc[i][6], 0.f); v1.w = fmaxf(acc[i][7], 0.f);
            *(float4*)&sH[(o0 + i) * 128 + k0] = v0;
            *(float4*)&sH[(o0 + i) * 128 + k0 + 4] = v1;
        }
    }
    __syncthreads();

    // ---- layer 2: 64 -> 64 (sH -> sX) ----
    {
        const int ot = tid >> 4, o0 = ot * 4;
        float acc[4][8];
#pragma unroll
        for (int i = 0; i < 4; i++) {
            float bb = sB1[o0 + i];
#pragma unroll
            for (int j = 0; j < 8; j++) acc[i][j] = bb;
        }
#pragma unroll 4
        for (int c = 0; c < 64; c++) {
            float4 wv = __ldg((const float4*)&g_w1t[c * 64 + o0]);
            float4 xa = *(const float4*)&sH[c * 128 + k0];
            float4 xb2 = *(const float4*)&sH[c * 128 + k0 + 4];
            float wr[4] = {wv.x, wv.y, wv.z, wv.w};
            float xr[8] = {xa.x, xa.y, xa.z, xa.w, xb2.x, xb2.y, xb2.z, xb2.w};
#pragma unroll
            for (int i = 0; i < 4; i++)
#pragma unroll
                for (int j = 0; j < 8; j++) acc[i][j] = fmaf(wr[i], xr[j], acc[i][j]);
        }
        __syncthreads();
#pragma unroll
        for (int i = 0; i < 4; i++) {
            float4 v0, v1;
            v0.x = fmaxf(acc[i][0], 0.f); v0.y = fmaxf(acc[i][1], 0.f);
            v0.z = fmaxf(acc[i][2], 0.f); v0.w = fmaxf(acc[i][3], 0.f);
            v1.x = fmaxf(acc[i][4], 0.f); v1.y = fmaxf(acc[i][5], 0.f);
            v1.z = fmaxf(acc[i][6], 0.f); v1.w = fmaxf(acc[i][7], 0.f);
            *(float4*)&sX[(o0 + i) * 128 + k0] = v0;
            *(float4*)&sX[(o0 + i) * 128 + k0 + 4] = v1;
        }
    }
    __syncthreads();

    // ---- layer 3: 64 -> 128 + max over K ----
    {
        const int ot = tid >> 4, o0 = ot * 8;
        float acc[8][8];
#pragma unroll
        for (int i = 0; i < 8; i++) {
            float bb = sB2[o0 + i];
#pragma unroll
            for (int j = 0; j < 8; j++) acc[i][j] = bb;
        }
#pragma unroll 2
        for (int c = 0; c < 64; c++) {
            float4 wa = __ldg((const float4*)&g_w2t[c * 128 + o0]);
            float4 wb = __ldg((const float4*)&g_w2t[c * 128 + o0 + 4]);
            float4 xa = *(const float4*)&sX[c * 128 + k0];
            float4 xb2 = *(const float4*)&sX[c * 128 + k0 + 4];
            float wr[8] = {wa.x, wa.y, wa.z, wa.w, wb.x, wb.y, wb.z, wb.w};
            float xr[8] = {xa.x, xa.y, xa.z, xa.w, xb2.x, xb2.y, xb2.z, xb2.w};
#pragma unroll
            for (int i = 0; i < 8; i++)
#pragma unroll
                for (int j = 0; j < 8; j++) acc[i][j] = fmaf(wr[i], xr[j], acc[i][j]);
        }
        int q = kt >> 3;
        int qg = qg0 + q, s = qg & 511;
#pragma unroll
        for (int i = 0; i < 8; i++) {
            float m = acc[i][0];
#pragma unroll
            for (int j = 1; j < 8; j++) m = fmaxf(m, acc[i][j]);
#pragma unroll
            for (int d = 1; d < 8; d <<= 1)
                m = fmaxf(m, __shfl_xor_sync(0xffffffffu, m, d));
            m = fmaxf(m, 0.0f);
            if ((kt & 7) == 0)
                out_pts[(size_t)b * 128 * SS + (size_t)(o0 + i) * SS + s] = m;
        }
    }
}

// ---------------------------------------------------------------------------
extern "C" void kernel_launch(void* const* d_in, const int* in_sizes, int n_in,
                              void* d_out, int out_size)
{
    const float* xyz  = (const float*)d_in[0];
    const float* pts  = (const float*)d_in[1];
    const float* attn = (const float*)d_in[2];
    const float* w0   = (const float*)d_in[3];
    const float* b0   = (const float*)d_in[4];
    const float* w1   = (const float*)d_in[5];
    const float* b1   = (const float*)d_in[6];
    const float* w2   = (const float*)d_in[7];
    const float* b2   = (const float*)d_in[8];

    float* out      = (float*)d_out;
    float* out_xyz  = out;                               // [B,3,S]
    float* out_pts  = out + BN * 3 * SS;                 // [B,128,S]
    float* out_attn = out + BN * 3 * SS + BN * 128 * SS; // [B,1,S]

    size_t fps_smem = (size_t)3 * NP * sizeof(float);     // 96 KB
    size_t mlp_smem = (size_t)17160 * sizeof(float);      // ~68.6 KB

    cudaFuncSetAttribute(fps_kernel, cudaFuncAttributeMaxDynamicSharedMemorySize, (int)fps_smem);
    cudaFuncSetAttribute(mlp_kernel, cudaFuncAttributeMaxDynamicSharedMemorySize, (int)mlp_smem);

    prep_kernel<<<65, 256>>>(w0, w1, w2);
    fps_kernel<<<dim3(2, BN), 512, fps_smem>>>(xyz, attn, out_xyz, out_attn);
    ball_kernel<<<BN * SS / 8, 256>>>(xyz, out_xyz);
    mlp_kernel<<<BN * SS / 2, 256, mlp_smem>>>(xyz, pts, b0, b1, b2, out_xyz, out_pts);
}

// round 5
// speedup vs baseline: 1.8963x; 1.2283x over previous
#include <cuda_runtime.h>

#define BN 8
#define NP 8192
#define SS 512
#define SA 128
#define SNN 384
#define KK 64
#define DF 64
#define C0 67

typedef unsigned long long ull;

__device__ int   g_nbr[BN * SS * KK];
__device__ __align__(16) float g_w0t[C0 * 64];
__device__ __align__(16) float g_w1t[64 * 64];
__device__ __align__(16) float g_w2t[64 * 128];
__device__ __align__(16) float g_ptsT[(size_t)BN * NP * DF];   // [B][N][D]

// ---- packed f32x2 helpers (Blackwell FFMA2 path, PTX-only) ----
__device__ __forceinline__ ull pk2(float lo, float hi) {
    ull r; asm("mov.b64 %0, {%1, %2};" : "=l"(r) : "f"(lo), "f"(hi)); return r;
}
__device__ __forceinline__ void upk2(ull v, float& lo, float& hi) {
    asm("mov.b64 {%0, %1}, %2;" : "=f"(lo), "=f"(hi) : "l"(v));
}
__device__ __forceinline__ ull ffma2(ull a, ull b, ull c) {
    ull d; asm("fma.rn.f32x2 %0, %1, %2, %3;" : "=l"(d) : "l"(a), "l"(b), "l"(c)); return d;
}
__device__ __forceinline__ ull fadd2(ull a, ull b) {
    ull d; asm("add.rn.f32x2 %0, %1, %2;" : "=l"(d) : "l"(a), "l"(b)); return d;
}

// ---------------------------------------------------------------------------
// Weight pre-transpose: w[o][c] -> wT[c][o], once, into device globals.
// ---------------------------------------------------------------------------
__global__ void prep_kernel(const float* __restrict__ w0,
                            const float* __restrict__ w1,
                            const float* __restrict__ w2)
{
    int t = blockIdx.x * 256 + threadIdx.x;
    if (t < 4288) {
        int o = t / C0, c = t - o * C0;
        g_w0t[c * 64 + o] = w0[t];
    } else if (t < 8384) {
        int i = t - 4288; int o = i >> 6, c = i & 63;
        g_w1t[c * 64 + o] = w1[i];
    } else if (t < 16576) {
        int i = t - 8384; int o = i >> 6, c = i & 63;
        g_w2t[c * 128 + o] = w2[i];
    }
}

// ---------------------------------------------------------------------------
// points transpose [B][D][N] -> [B][N][D] via 32x32 smem tiles.
// ---------------------------------------------------------------------------
__global__ void transpose_pts(const float* __restrict__ pts)
{
    __shared__ float tile[32][33];
    int b = blockIdx.z;
    int n0 = blockIdx.x * 32, d0 = blockIdx.y * 32;
    int tx = threadIdx.x, ty = threadIdx.y;
#pragma unroll
    for (int i = ty; i < 32; i += 8)
        tile[i][tx] = pts[((size_t)b * DF + d0 + i) * NP + n0 + tx];
    __syncthreads();
#pragma unroll
    for (int i = ty; i < 32; i += 8)
        g_ptsT[((size_t)b * NP + n0 + i) * DF + d0 + tx] = tile[tx][i];
}

// ---------------------------------------------------------------------------
// FPS main loop (round-3 proven variant: REDUX value + equality-index +
// atomicMin, 2 barriers). Slot order preserves original index order.
// ---------------------------------------------------------------------------
template<int P>
__device__ void fps_loop(const float* cx, const float* cy, const float* cz,
                         int last, int Ksel, int off, int b, int which,
                         int M, int Mr,
                         float* out_xyz, float* out_attn,
                         unsigned* warpmax, int* s_best)
{
    const int tid = threadIdx.x, lane = tid & 31, wid = tid >> 5;
    const int base = tid * 2 * P;

    ull pxu[P], pyu[P], pzu[P], pnu[P];
    float mdlo[P], mdhi[P];
#pragma unroll
    for (int p = 0; p < P; p++) {
        float x0 = cx[base + 2 * p],     y0 = cy[base + 2 * p],     z0 = cz[base + 2 * p];
        float x1 = cx[base + 2 * p + 1], y1 = cy[base + 2 * p + 1], z1 = cz[base + 2 * p + 1];
        pxu[p] = pk2(x0, x1); pyu[p] = pk2(y0, y1); pzu[p] = pk2(z0, z1);
        pnu[p] = pk2(fmaf(z0, z0, fmaf(y0, y0, x0 * x0)),
                     fmaf(z1, z1, fmaf(y1, y1, x1 * x1)));
        mdlo[p] = (base + 2 * p)     < Mr ? 1e10f : -1e30f;
        mdhi[p] = (base + 2 * p + 1) < Mr ? 1e10f : -1e30f;
    }

    const float keep_val = (which == 0) ? 1.0f : 0.0f;
    int parity = 0;
    for (int k = 0;; k++) {
        float lx = cx[last], ly = cy[last], lz = cz[last];
        if (tid == 0) {
            int o = off + k;
            out_xyz[(size_t)b * 3 * SS + o]          = lx;
            out_xyz[(size_t)b * 3 * SS + SS + o]     = ly;
            out_xyz[(size_t)b * 3 * SS + 2 * SS + o] = lz;
            out_attn[(size_t)b * SS + o] = (last < M) ? keep_val : 1.0f - keep_val;
        }
        if (k == Ksel - 1) break;

        float ln = fmaf(lz, lz, fmaf(ly, ly, lx * lx));
        ull lx2 = pk2(-2.0f * lx, -2.0f * lx);
        ull ly2 = pk2(-2.0f * ly, -2.0f * ly);
        ull lz2 = pk2(-2.0f * lz, -2.0f * lz);
        ull lnp = pk2(ln, ln);

        float tmax = -1e30f;
#pragma unroll
        for (int p = 0; p < P; p++) {
            ull e = ffma2(pzu[p], lz2, ffma2(pyu[p], ly2, ffma2(pxu[p], lx2, pnu[p])));
            e = fadd2(e, lnp);
            float elo, ehi; upk2(e, elo, ehi);
            mdlo[p] = fminf(mdlo[p], elo);
            mdhi[p] = fminf(mdhi[p], ehi);
            tmax = fmaxf(tmax, fmaxf(mdlo[p], mdhi[p]));
        }
        unsigned tc = __float_as_uint(fmaxf(tmax, 0.0f));
        unsigned wm = __reduce_max_sync(0xffffffffu, tc);
        if (lane == 0) warpmax[wid] = wm;
        __syncthreads();

        if (tid == 0) s_best[parity ^ 1] = 0x7fffffff;
        unsigned W = warpmax[0];
#pragma unroll
        for (int w = 1; w < 16; w++) W = max(W, warpmax[w]);

        if (tc == W) {
            float Wf = __uint_as_float(W);
            int bi = 0x7fffffff;
#pragma unroll
            for (int p = 0; p < P; p++) {
                bi = min(bi, (mdlo[p] == Wf) ? (base + 2 * p)     : 0x7fffffff);
                bi = min(bi, (mdhi[p] == Wf) ? (base + 2 * p + 1) : 0x7fffffff);
            }
            if (bi != 0x7fffffff) atomicMin(&s_best[parity], bi);
        }
        __syncthreads();
        last = s_best[parity];
        parity ^= 1;
    }
}

// ---------------------------------------------------------------------------
// FPS driver: compaction (kept points + one zero-representative) then loop.
// ---------------------------------------------------------------------------
__global__ __launch_bounds__(512, 1) void fps_kernel(
    const float* __restrict__ xyz, const float* __restrict__ attn,
    float* __restrict__ out_xyz, float* __restrict__ out_attn)
{
    extern __shared__ float sm[];
    float* cx = sm;
    float* cy = sm + NP;
    float* cz = sm + 2 * NP;
    __shared__ int s_wsum[16];
    __shared__ int s_woff[16];
    __shared__ unsigned warpmax[16];
    __shared__ int s_best[2];
    __shared__ int s_zero;
    __shared__ int s_M;

    const int tid = threadIdx.x;
    const int lane = tid & 31, wid = tid >> 5;
    const int b = blockIdx.y;
    const int which = blockIdx.x;
    const int Ksel = (which == 0) ? SA : SNN;
    const int off  = (which == 0) ? 0 : SA;

    const float* xb = xyz + (size_t)b * 3 * NP;
    const float* ab = attn + (size_t)b * NP;

    if (tid == 0) { s_zero = 0x7fffffff; s_best[0] = 0x7fffffff; s_best[1] = 0x7fffffff; }

    const int ibase = tid * 16;
    float xv[16], yv[16], zv[16];
    unsigned km = 0;
    int zm = 0x7fffffff;
#pragma unroll
    for (int j4 = 0; j4 < 4; j4++) {
        float4 a4 = *(const float4*)&ab[ibase + j4 * 4];
        float4 x4 = *(const float4*)&xb[ibase + j4 * 4];
        float4 y4 = *(const float4*)&xb[NP + ibase + j4 * 4];
        float4 z4 = *(const float4*)&xb[2 * NP + ibase + j4 * 4];
        float aa[4] = {a4.x, a4.y, a4.z, a4.w};
        float xx[4] = {x4.x, x4.y, x4.z, x4.w};
        float yy[4] = {y4.x, y4.y, y4.z, y4.w};
        float zz[4] = {z4.x, z4.y, z4.z, z4.w};
#pragma unroll
        for (int q = 0; q < 4; q++) {
            int j = j4 * 4 + q;
            float f = (which == 0) ? aa[q] : 1.0f - aa[q];
            xv[j] = xx[q]; yv[j] = yy[q]; zv[j] = zz[q];
            if (f != 0.0f) km |= 1u << j;
            else zm = min(zm, ibase + j);
        }
    }
    int cnt = __popc(km);

    int incl = cnt;
#pragma unroll
    for (int d = 1; d < 32; d <<= 1) {
        int v = __shfl_up_sync(0xffffffffu, incl, d);
        if (lane >= d) incl += v;
    }
    if (lane == 31) s_wsum[wid] = incl;
    if (zm != 0x7fffffff) atomicMin(&s_zero, zm);
    __syncthreads();
    if (tid < 16) {
        int v = s_wsum[tid];
        int iv = v;
#pragma unroll
        for (int d = 1; d < 16; d <<= 1) {
            int t = __shfl_up_sync(0x0000ffffu, iv, d);
            if (tid >= d) iv += t;
        }
        s_woff[tid] = iv - v;
        if (tid == 15) s_M = iv;
    }
    __syncthreads();

    int pos = s_woff[wid] + incl - cnt;
#pragma unroll
    for (int j = 0; j < 16; j++) {
        if ((km >> j) & 1u) {
            cx[pos] = xv[j]; cy[pos] = yv[j]; cz[pos] = zv[j];
            pos++;
        }
    }
    __syncthreads();

    const int M = s_M;
    int Mr = M;
    if (s_zero != 0x7fffffff) {
        if (tid == 0) { cx[M] = 0.0f; cy[M] = 0.0f; cz[M] = 0.0f; }
        Mr = M + 1;
    }
    int P = (Mr + 1023) >> 10;
    if (P < 1) P = 1;
    int Npad = P << 10;
    for (int i = Mr + tid; i < Npad; i += 512) { cx[i] = 0.0f; cy[i] = 0.0f; cz[i] = 0.0f; }
    __syncthreads();

    float a0 = ab[0];
    float f0 = (which == 0) ? a0 : 1.0f - a0;
    int last = (f0 != 0.0f) ? 0 : M;

    switch (P) {
        case 1: fps_loop<1>(cx, cy, cz, last, Ksel, off, b, which, M, Mr, out_xyz, out_attn, warpmax, s_best); break;
        case 2: fps_loop<2>(cx, cy, cz, last, Ksel, off, b, which, M, Mr, out_xyz, out_attn, warpmax, s_best); break;
        case 3: fps_loop<3>(cx, cy, cz, last, Ksel, off, b, which, M, Mr, out_xyz, out_attn, warpmax, s_best); break;
        case 4: fps_loop<4>(cx, cy, cz, last, Ksel, off, b, which, M, Mr, out_xyz, out_attn, warpmax, s_best); break;
        case 5: fps_loop<5>(cx, cy, cz, last, Ksel, off, b, which, M, Mr, out_xyz, out_attn, warpmax, s_best); break;
        case 6: fps_loop<6>(cx, cy, cz, last, Ksel, off, b, which, M, Mr, out_xyz, out_attn, warpmax, s_best); break;
        case 7: fps_loop<7>(cx, cy, cz, last, Ksel, off, b, which, M, Mr, out_xyz, out_attn, warpmax, s_best); break;
        default: fps_loop<8>(cx, cy, cz, last, Ksel, off, b, which, M, Mr, out_xyz, out_attn, warpmax, s_best); break;
    }
}

// ---------------------------------------------------------------------------
// Ball query: one warp per query, first KK in index order, pad -1.
// ---------------------------------------------------------------------------
__global__ __launch_bounds__(256, 1) void ball_kernel(
    const float* __restrict__ xyz, const float* __restrict__ new_xyz)
{
    int w = blockIdx.x * 8 + (threadIdx.x >> 5);
    int lane = threadIdx.x & 31;
    int b = w >> 9, s = w & 511;
    const float R2 = (float)(0.4 * 0.4);

    float qx = new_xyz[(size_t)b * 3 * SS + s];
    float qy = new_xyz[(size_t)b * 3 * SS + SS + s];
    float qz = new_xyz[(size_t)b * 3 * SS + 2 * SS + s];
    const float* xb = xyz + (size_t)b * 3 * NP;
    int* out = g_nbr + (size_t)w * KK;

    int cnt = 0;
    for (int base = 0; base < NP; base += 32) {
        int i = base + lane;
        float dx = xb[i] - qx, dy = xb[NP + i] - qy, dz = xb[2 * NP + i] - qz;
        float d2 = fmaf(dz, dz, fmaf(dy, dy, dx * dx));
        bool m = d2 < R2;
        unsigned bal = __ballot_sync(0xffffffffu, m);
        int rank = cnt + __popc(bal & ((1u << lane) - 1u));
        if (m && rank < KK) out[rank] = i;
        cnt += __popc(bal);
        if (cnt >= KK) break;
    }
    if (cnt > KK) cnt = KK;
    for (int j = cnt + lane; j < KK; j += 32) out[j] = -1;
}

// ---------------------------------------------------------------------------
// MLP 67->64->64->128 + ReLU + max over K.
// Block = 4 queries = 256 cols, 256 threads, 8x8 register tiles.
// Thread (ot = tid>>5, lane) covers outs o0..o0+7 and cols {4*lane..+3,
// 128+4*lane..+3}  => both LDS.128 are warp-consecutive (conflict-free);
// weight loads are warp-broadcast __ldg from pre-transposed globals.
// smem (floats): sX @0 (67*256=17152), sH @17152 (64*256=16384),
//                sB0 @33536, sB1 @33600, sB2 @33664, sIdx @33792, sQ @34048
// ---------------------------------------------------------------------------
__global__ __launch_bounds__(256, 1) void mlp_kernel(
    const float* __restrict__ xyz,
    const float* __restrict__ b0, const float* __restrict__ b1,
    const float* __restrict__ b2,
    const float* __restrict__ new_xyz, float* __restrict__ out_pts)
{
    extern __shared__ float sm[];
    float* sX   = sm;
    float* sH   = sm + 17152;
    float* sB0  = sm + 33536;
    float* sB1  = sm + 33600;
    float* sB2  = sm + 33664;
    int*   sIdx = (int*)(sm + 33792);
    float* sQ   = sm + 34048;

    const int tid = threadIdx.x;
    const int qg0 = blockIdx.x * 4;
    const int b = qg0 >> 9;

    if (tid < 64)  sB0[tid] = b0[tid];
    if (tid >= 64 && tid < 128) sB1[tid - 64] = b1[tid - 64];
    if (tid >= 128) sB2[tid - 128] = b2[tid - 128];
    sIdx[tid] = g_nbr[(size_t)qg0 * KK + tid];
    if (tid < 4) {
        int qg = qg0 + tid, s = qg & 511;
        sQ[tid * 3 + 0] = new_xyz[(size_t)b * 3 * SS + s];
        sQ[tid * 3 + 1] = new_xyz[(size_t)b * 3 * SS + SS + s];
        sQ[tid * 3 + 2] = new_xyz[(size_t)b * 3 * SS + 2 * SS + s];
    }
    __syncthreads();

    // ---- gather X [67][256]: one thread per column ----
    {
        const int col = tid, q = col >> 6;
        int id = sIdx[col];
        int gid = (id < 0) ? NP - 1 : id;
        float qx = sQ[q * 3], qy = sQ[q * 3 + 1], qz = sQ[q * 3 + 2];
        const float* xyzB = xyz + (size_t)b * 3 * NP;
        if (id < 0) { sX[col] = -qx; sX[256 + col] = -qy; sX[512 + col] = -qz; }
        else {
            sX[col]       = xyzB[id] - qx;
            sX[256 + col] = xyzB[NP + id] - qy;
            sX[512 + col] = xyzB[2 * NP + id] - qz;
        }
        const float4* p4 = (const float4*)&g_ptsT[((size_t)b * NP + gid) * DF];
#pragma unroll
        for (int d4 = 0; d4 < 16; d4++) {
            float4 v = __ldg(&p4[d4]);
            sX[(3 + 4 * d4) * 256 + col]     = v.x;
            sX[(3 + 4 * d4 + 1) * 256 + col] = v.y;
            sX[(3 + 4 * d4 + 2) * 256 + col] = v.z;
            sX[(3 + 4 * d4 + 3) * 256 + col] = v.w;
        }
    }
    __syncthreads();

    const int ot = tid >> 5, lane = tid & 31;
    const int o0 = ot * 8;
    const int c0a = lane * 4, c0b = 128 + lane * 4;

    // ---- layer 1: 67 -> 64, sX -> sH ----
    {
        float acc[8][8];
#pragma unroll
        for (int i = 0; i < 8; i++) {
            float bb = sB0[o0 + i];
#pragma unroll
            for (int j = 0; j < 8; j++) acc[i][j] = bb;
        }
#pragma unroll 4
        for (int c = 0; c < C0; c++) {
            float4 wa = __ldg((const float4*)&g_w0t[c * 64 + o0]);
            float4 wb = __ldg((const float4*)&g_w0t[c * 64 + o0 + 4]);
            float4 xa = *(const float4*)&sX[c * 256 + c0a];
            float4 xb2 = *(const float4*)&sX[c * 256 + c0b];
            float wr[8] = {wa.x, wa.y, wa.z, wa.w, wb.x, wb.y, wb.z, wb.w};
            float xr[8] = {xa.x, xa.y, xa.z, xa.w, xb2.x, xb2.y, xb2.z, xb2.w};
#pragma unroll
            for (int i = 0; i < 8; i++)
#pragma unroll
                for (int j = 0; j < 8; j++) acc[i][j] = fmaf(wr[i], xr[j], acc[i][j]);
        }
#pragma unroll
        for (int i = 0; i < 8; i++) {
            float4 v0, v1;
            v0.x = fmaxf(acc[i][0], 0.f); v0.y = fmaxf(acc[i][1], 0.f);
            v0.z = fmaxf(acc[i][2], 0.f); v0.w = fmaxf(acc[i][3], 0.f);
            v1.x = fmaxf(acc[i][4], 0.f); v1.y = fmaxf(acc[i][5], 0.f);
            v1.z = fmaxf(acc[i][6], 0.f); v1.w = fmaxf(acc[i][7], 0.f);
            *(float4*)&sH[(o0 + i) * 256 + c0a] = v0;
            *(float4*)&sH[(o0 + i) * 256 + c0b] = v1;
        }
    }
    __syncthreads();

    // ---- layer 2: 64 -> 64, sH -> sX rows 0..63 ----
    {
        float acc[8][8];
#pragma unroll
        for (int i = 0; i < 8; i++) {
            float bb = sB1[o0 + i];
#pragma unroll
            for (int j = 0; j < 8; j++) acc[i][j] = bb;
        }
#pragma unroll 4
        for (int c = 0; c < 64; c++) {
            float4 wa = __ldg((const float4*)&g_w1t[c * 64 + o0]);
            float4 wb = __ldg((const float4*)&g_w1t[c * 64 + o0 + 4]);
            float4 xa = *(const float4*)&sH[c * 256 + c0a];
            float4 xb2 = *(const float4*)&sH[c * 256 + c0b];
            float wr[8] = {wa.x, wa.y, wa.z, wa.w, wb.x, wb.y, wb.z, wb.w};
            float xr[8] = {xa.x, xa.y, xa.z, xa.w, xb2.x, xb2.y, xb2.z, xb2.w};
#pragma unroll
            for (int i = 0; i < 8; i++)
#pragma unroll
                for (int j = 0; j < 8; j++) acc[i][j] = fmaf(wr[i], xr[j], acc[i][j]);
        }
        // layer2 writes sX rows 0..63 (layer-1 inputs, now dead); all threads
        // are past their sX reads only after the barrier below guards layer3.
#pragma unroll
        for (int i = 0; i < 8; i++) {
            float4 v0, v1;
            v0.x = fmaxf(acc[i][0], 0.f); v0.y = fmaxf(acc[i][1], 0.f);
            v0.z = fmaxf(acc[i][2], 0.f); v0.w = fmaxf(acc[i][3], 0.f);
            v1.x = fmaxf(acc[i][4], 0.f); v1.y = fmaxf(acc[i][5], 0.f);
            v1.z = fmaxf(acc[i][6], 0.f); v1.w = fmaxf(acc[i][7], 0.f);
            *(float4*)&sX[(o0 + i) * 256 + c0a] = v0;
            *(float4*)&sX[(o0 + i) * 256 + c0b] = v1;
        }
    }
    __syncthreads();

    // ---- layer 3: 64 -> 128 (two 64-out passes) + max over K ----
    const int qa = lane >> 4;          // cols 4*lane       -> query qa
    const int sa = (qg0 + qa) & 511;   // cols 128+4*lane   -> query qa+2
    const int sb2_ = (qg0 + qa + 2) & 511;
#pragma unroll
    for (int pass = 0; pass < 2; pass++) {
        const int op = pass * 64 + o0;
        float acc[8][8];
#pragma unroll
        for (int i = 0; i < 8; i++) {
            float bb = sB2[op + i];
#pragma unroll
            for (int j = 0; j < 8; j++) acc[i][j] = bb;
        }
#pragma unroll 4
        for (int c = 0; c < 64; c++) {
            float4 wa = __ldg((const float4*)&g_w2t[c * 128 + op]);
            float4 wb = __ldg((const float4*)&g_w2t[c * 128 + op + 4]);
            float4 xa = *(const float4*)&sX[c * 256 + c0a];
            float4 xb2 = *(const float4*)&sX[c * 256 + c0b];
            float wr[8] = {wa.x, wa.y, wa.z, wa.w, wb.x, wb.y, wb.z, wb.w};
            float xr[8] = {xa.x, xa.y, xa.z, xa.w, xb2.x, xb2.y, xb2.z, xb2.w};
#pragma unroll
            for (int i = 0; i < 8; i++)
#pragma unroll
                for (int j = 0; j < 8; j++) acc[i][j] = fmaf(wr[i], xr[j], acc[i][j]);
        }
#pragma unroll
        for (int i = 0; i < 8; i++) {
            float ma = fmaxf(fmaxf(acc[i][0], acc[i][1]), fmaxf(acc[i][2], acc[i][3]));
            float mb = fmaxf(fmaxf(acc[i][4], acc[i][5]), fmaxf(acc[i][6], acc[i][7]));
#pragma unroll
            for (int d = 1; d < 16; d <<= 1) {
                ma = fmaxf(ma, __shfl_xor_sync(0xffffffffu, ma, d));
                mb = fmaxf(mb, __shfl_xor_sync(0xffffffffu, mb, d));
            }
            if ((lane & 15) == 0) {
                out_pts[(size_t)b * 128 * SS + (size_t)(op + i) * SS + sa]   = fmaxf(ma, 0.0f);
                out_pts[(size_t)b * 128 * SS + (size_t)(op + i) * SS + sb2_] = fmaxf(mb, 0.0f);
            }
        }
    }
}

// ---------------------------------------------------------------------------
extern "C" void kernel_launch(void* const* d_in, const int* in_sizes, int n_in,
                              void* d_out, int out_size)
{
    const float* xyz  = (const float*)d_in[0];
    const float* pts  = (const float*)d_in[1];
    const float* attn = (const float*)d_in[2];
    const float* w0   = (const float*)d_in[3];
    const float* b0   = (const float*)d_in[4];
    const float* w1   = (const float*)d_in[5];
    const float* b1   = (const float*)d_in[6];
    const float* w2   = (const float*)d_in[7];
    const float* b2   = (const float*)d_in[8];

    float* out      = (float*)d_out;
    float* out_xyz  = out;                               // [B,3,S]
    float* out_pts  = out + BN * 3 * SS;                 // [B,128,S]
    float* out_attn = out + BN * 3 * SS + BN * 128 * SS; // [B,1,S]

    size_t fps_smem = (size_t)3 * NP * sizeof(float);     // 96 KB
    size_t mlp_smem = (size_t)34064 * sizeof(float);      // ~136 KB

    cudaFuncSetAttribute(fps_kernel, cudaFuncAttributeMaxDynamicSharedMemorySize, (int)fps_smem);
    cudaFuncSetAttribute(mlp_kernel, cudaFuncAttributeMaxDynamicSharedMemorySize, (int)mlp_smem);

    prep_kernel<<<65, 256>>>(w0, w1, w2);
    transpose_pts<<<dim3(NP / 32, DF / 32, BN), dim3(32, 8)>>>(pts);
    fps_kernel<<<dim3(2, BN), 512, fps_smem>>>(xyz, attn, out_xyz, out_attn);
    ball_kernel<<<BN * SS / 8, 256>>>(xyz, out_xyz);
    mlp_kernel<<<BN * SS / 4, 256, mlp_smem>>>(xyz, b0, b1, b2, out_xyz, out_pts);
}